// round 12
// baseline (speedup 1.0000x reference)
#include <cuda_runtime.h>
#include <cuda_bf16.h>
#include <mma.h>
#include <math.h>
#include <stdint.h>

using namespace nvcuda;

// Problem constants
#define TT   4096
#define DM   1024
#define HH   16
#define HD   64
#define DFFc 2048
#define EE   8
#define SS   2048
#define BB   2

typedef __nv_bfloat16 bf16;

// ---------------- scratch ----------------
__device__ float g_rkv[3 * TT * DM];
__device__ float g_yf[TT * DM];
__device__ float g_yb[TT * DM];
__device__ float g_x1[TT * DM];
__device__ float g_xn2[TT * DM];
__device__ float g_moe[2 * TT * DM];
__device__ bf16  g_xn1h[TT * DM],  g_xn1l[TT * DM];
__device__ bf16  g_yah[TT * DM],   g_yal[TT * DM];
__device__ bf16  g_xn2h[TT * DM],  g_xn2l[TT * DM];
__device__ bf16  g_hh[2 * TT * DFFc], g_hl[2 * TT * DFFc];
__device__ bf16  g_wqkvh[3 * DM * DM], g_wqkvl[3 * DM * DM];
__device__ bf16  g_woh[DM * DM],   g_wol[DM * DM];
__device__ bf16  g_w1h[EE * DFFc * DM], g_w1l[EE * DFFc * DM];
__device__ bf16  g_w2h[EE * DM * DFFc], g_w2l[EE * DM * DFFc];
__device__ float g_gate[2 * TT];
__device__ int   g_list[EE * TT];
__device__ int   g_cnt[EE];
__device__ float g_pmean[EE];

__device__ __forceinline__ uint32_t smem_u32(const void* p) {
    uint32_t a;
    asm("{ .reg .u64 t; cvta.to.shared.u64 t, %1; cvt.u32.u64 %0, t; }" : "=r"(a) : "l"(p));
    return a;
}
__device__ __forceinline__ void cp_async16(uint32_t s, const void* g) {
    asm volatile("cp.async.cg.shared.global [%0], [%1], 16;" :: "r"(s), "l"(g) : "memory");
}
#define CP_COMMIT() asm volatile("cp.async.commit_group;" ::: "memory")
#define CP_WAIT1()  asm volatile("cp.async.wait_group 1;"  ::: "memory")

// ---------------- small kernels ----------------
__global__ void zero_k() {
    int i = threadIdx.x;
    if (i < EE) { g_cnt[i] = 0; g_pmean[i] = 0.f; }
}

// transpose + split: src [K,N] fp32 (batch z) -> dh/dl [N,K] bf16 (vectorized stores)
__global__ void tsplit_k(const float* __restrict__ src, bf16* __restrict__ dh,
                         bf16* __restrict__ dl, int K, int N) {
    int e = blockIdx.z;
    src += (size_t)e * K * N;
    dh  += (size_t)e * N * K;
    dl  += (size_t)e * N * K;
    __shared__ float tile[32][33];
    int n0 = blockIdx.x * 32, k0 = blockIdx.y * 32;
    int tx = threadIdx.x, ty = threadIdx.y;
#pragma unroll
    for (int i = 0; i < 4; i++)
        tile[ty + i * 8][tx] = src[(size_t)(k0 + ty + i * 8) * N + n0 + tx];
    __syncthreads();
    int t = ty * 32 + tx;
#pragma unroll
    for (int it = 0; it < 2; it++) {
        int i = t + it * 256;
        int row = i >> 4;
        int kp  = i & 15;
        float v0 = tile[kp * 2][row];
        float v1 = tile[kp * 2 + 1][row];
        bf16 h0 = __float2bfloat16_rn(v0);
        bf16 h1 = __float2bfloat16_rn(v1);
        __nv_bfloat162 hv; hv.x = h0; hv.y = h1;
        __nv_bfloat162 lv;
        lv.x = __float2bfloat16_rn(v0 - __bfloat162float(h0));
        lv.y = __float2bfloat16_rn(v1 - __bfloat162float(h1));
        size_t o = ((size_t)(n0 + row) * K + k0 + kp * 2) >> 1;
        ((__nv_bfloat162*)dh)[o] = hv;
        ((__nv_bfloat162*)dl)[o] = lv;
    }
}

__global__ void splitadd_k(const float* __restrict__ a, const float* __restrict__ b,
                           bf16* __restrict__ hi, bf16* __restrict__ lo, int n) {
    int i = blockIdx.x * blockDim.x + threadIdx.x;
    if (i >= n) return;
    float v = a[i] + b[i];
    bf16 h = __float2bfloat16_rn(v);
    hi[i] = h;
    lo[i] = __float2bfloat16_rn(v - __bfloat162float(h));
}

template <bool WRITE_F32>
__global__ void rmsnorm_k(const float* __restrict__ x, const float* __restrict__ w,
                          float* __restrict__ ofp, bf16* __restrict__ ohi, bf16* __restrict__ olo) {
    int t = blockIdx.x;
    const float* xr = x + (size_t)t * DM;
    float s = 0.f;
    for (int i = threadIdx.x; i < DM; i += 256) { float v = xr[i]; s += v * v; }
    for (int off = 16; off; off >>= 1) s += __shfl_xor_sync(0xffffffffu, s, off);
    __shared__ float red[8];
    int wrp = threadIdx.x >> 5, ln = threadIdx.x & 31;
    if (ln == 0) red[wrp] = s;
    __syncthreads();
    if (wrp == 0) {
        float v = (ln < 8) ? red[ln] : 0.f;
        for (int off = 4; off; off >>= 1) v += __shfl_xor_sync(0xffffffffu, v, off);
        if (ln == 0) red[0] = v;
    }
    __syncthreads();
    float scale = rsqrtf(red[0] / (float)DM + 1e-6f);
    size_t base = (size_t)t * DM;
    for (int i = threadIdx.x; i < DM; i += 256) {
        float v = xr[i] * scale * w[i];
        if (WRITE_F32) ofp[base + i] = v;
        bf16 h = __float2bfloat16_rn(v);
        ohi[base + i] = h;
        olo[base + i] = __float2bfloat16_rn(v - __bfloat162float(h));
    }
}

// ---------------- RWKV bidirectional scan (R6 version) ----------------
__global__ void scan_k(const float* __restrict__ r, const float* __restrict__ k,
                       const float* __restrict__ v,
                       const float* __restrict__ decay, const float* __restrict__ bonus) {
    int h  = blockIdx.x >> 1;
    int vh = blockIdx.x & 1;
    int b  = blockIdx.y;
    int dir = blockIdx.z;
    int tid = threadIdx.x;
    int vcol  = vh * 32 + (tid >> 2);
    int kc    = tid & 3;
    int kbase = kc * 16;

    float Sst[16], wr_[16], ur_[16];
#pragma unroll
    for (int i = 0; i < 16; i++) {
        Sst[i] = 0.f;
        float d = decay[h * HD + kbase + i];
        wr_[i] = expf(-expf(d));
        ur_[i] = bonus[h * HD + kbase + i];
    }
    float* yo = dir ? g_yb : g_yf;

    __shared__ float s_r[2][64], s_k[2][64];
    for (int s = 0; s < SS; s++) {
        int idx = dir ? (SS - 1 - s) : s;
        size_t base = ((size_t)(b * SS + idx)) * DM + h * HD;
        int bf = s & 1;
        if (tid < 64)       s_r[bf][tid]      = r[base + tid];
        else                s_k[bf][tid - 64] = k[base + tid - 64];
        float vv = v[base + vcol];
        __syncthreads();
        float y = 0.f;
#pragma unroll
        for (int i = 0; i < 16; i++) {
            float kk  = s_k[bf][kbase + i];
            float rr  = s_r[bf][kbase + i];
            float kv  = kk * vv;
            float tmp = fmaf(ur_[i], kv, Sst[i]);
            y = fmaf(rr, tmp, y);
            Sst[i] = fmaf(wr_[i], Sst[i], kv);
        }
        y += __shfl_xor_sync(0xffffffffu, y, 1);
        y += __shfl_xor_sync(0xffffffffu, y, 2);
        if (kc == 0) yo[base + vcol] = y;
    }
}

// ---------------- router ----------------
__global__ void router_k(const float* __restrict__ xn2, const float* __restrict__ rw) {
    int t = blockIdx.x, tid = threadIdx.x;
    __shared__ float sx[DM];
    __shared__ float slog[8];
    const float* xr = xn2 + (size_t)t * DM;
    for (int i = tid; i < DM; i += 256) sx[i] = xr[i];
    __syncthreads();
    int w = tid >> 5, l = tid & 31;
    float acc = 0.f;
    for (int d = l; d < DM; d += 32) acc = fmaf(sx[d], rw[d * EE + w], acc);
    for (int off = 16; off; off >>= 1) acc += __shfl_xor_sync(0xffffffffu, acc, off);
    if (l == 0) slog[w] = acc;
    __syncthreads();
    if (tid == 0) {
        float mx = -1e30f;
        for (int e = 0; e < EE; e++) mx = fmaxf(mx, slog[e]);
        float p[EE], sum = 0.f;
        for (int e = 0; e < EE; e++) { p[e] = expf(slog[e] - mx); sum += p[e]; }
        float inv = 1.f / sum;
        int e0 = 0; float b0 = -1.f;
        for (int e = 0; e < EE; e++) { p[e] *= inv; if (p[e] > b0) { b0 = p[e]; e0 = e; } }
        int e1 = -1; float b1 = -1.f;
        for (int e = 0; e < EE; e++) { if (e == e0) continue; if (p[e] > b1) { b1 = p[e]; e1 = e; } }
        float gs = 1.f / (b0 + b1);
        g_gate[2 * t]     = b0 * gs;
        g_gate[2 * t + 1] = b1 * gs;
        int pos0 = atomicAdd(&g_cnt[e0], 1); g_list[e0 * TT + pos0] = 2 * t;
        int pos1 = atomicAdd(&g_cnt[e1], 1); g_list[e1 * TT + pos1] = 2 * t + 1;
        for (int e = 0; e < EE; e++) atomicAdd(&g_pmean[e], p[e]);
    }
}

// ---------------- WMMA bf16 split GEMM, 2-stage cp.async, BK=64, 512 threads ----------------
// CTA tile BMT x 256, BK=64, 16 warps (2M x 8N), warp tile (BMT/2) x 32.
// D = Ah*Bh + Ah*Bl + Al*Bh   (fp32 accumulate)
#define NT   512
#define BNw 256
#define BKw 64
#define LDT 72
#define B_TYPE_B  (256 * LDT * 2)          // 36864 bytes
#define CLD 260                            // epilogue fp32 ld

template <int BMT> struct GCfg {
    static constexpr int ATB   = BMT * LDT * 2;
    static constexpr int STAGE = 2 * ATB + 2 * B_TYPE_B;
    static constexpr int SMEM  = 2 * STAGE;
};

template <int MODE, int BMT>
__global__ void __launch_bounds__(NT, 1)
wgemm_k(const bf16* __restrict__ Ah, const bf16* __restrict__ Al,
        const bf16* __restrict__ Bh, const bf16* __restrict__ Bl,
        const float* __restrict__ resid, float* __restrict__ Cf,
        bf16* __restrict__ Chh, bf16* __restrict__ Chl,
        int M, int N, int K) {
    constexpr int MI   = BMT / 32;      // a-frags per warp (warp covers BMT/2 rows)
    constexpr int AITS = BMT / 64;      // BMT rows * 8 segs / 512 threads
    constexpr int ATB  = GCfg<BMT>::ATB;
    constexpr int STG  = GCfg<BMT>::STAGE;
    constexpr int NPASS = BMT / 64;

    int z = blockIdx.z;
    int bx = blockIdx.x, by = blockIdx.y;
    int Mrows = M;
    const int* list = nullptr;
    if (MODE == 2 || MODE == 3) { Mrows = g_cnt[z]; list = g_list + z * TT; }
    if (by * BMT >= Mrows) return;

    size_t boff = 0;
    if (MODE == 0) boff = (size_t)z * DM * DM;
    if (MODE == 2) boff = (size_t)z * DFFc * DM;
    if (MODE == 3) boff = (size_t)z * DM * DFFc;
    const bf16* bhg = Bh + boff;
    const bf16* blg = Bl + boff;
    float* cf = Cf;
    if (MODE == 0) cf = Cf + (size_t)z * TT * DM;

    extern __shared__ char smem[];
    uint32_t sb = smem_u32(smem);

    int tid = threadIdx.x;
    int wid = tid >> 5;
    int wm = wid & 1;          // M half (BMT/2 rows)
    int wn = wid >> 1;         // 32-col slice (0..7)

    // loads: rows have 8 segs of 16B (64 bf16 per chunk-row)
    size_t a_src[AITS]; uint32_t a_so[AITS];
#pragma unroll
    for (int it = 0; it < AITS; it++) {
        int idx = tid + it * NT;
        int row = idx >> 3, seg = idx & 7;
        int ar = by * BMT + row;
        if (MODE == 2 || MODE == 3) {
            int rc = ar < Mrows ? ar : (Mrows - 1);
            int p = list[rc];
            ar = (MODE == 2) ? (p >> 1) : p;
        }
        a_src[it] = (size_t)ar * K + seg * 8;
        a_so[it] = (uint32_t)((row * LDT + seg * 8) * 2);
    }
    size_t b_src[4]; uint32_t b_so[4];
#pragma unroll
    for (int it = 0; it < 4; it++) {
        int idx = tid + it * NT;
        int row = idx >> 3, seg = idx & 7;
        b_src[it] = (size_t)(bx * BNw + row) * K + seg * 8;
        b_so[it] = (uint32_t)((row * LDT + seg * 8) * 2);
    }

    const int NC = K / BKw;
    auto issue = [&](int ci, int buf) {
        if (ci < NC) {
            int k0 = ci * BKw;
            uint32_t base = sb + buf * STG;
#pragma unroll
            for (int it = 0; it < AITS; it++) {
                cp_async16(base + a_so[it],       Ah + a_src[it] + k0);
                cp_async16(base + ATB + a_so[it], Al + a_src[it] + k0);
            }
#pragma unroll
            for (int it = 0; it < 4; it++) {
                cp_async16(base + 2 * ATB + b_so[it],            bhg + b_src[it] + k0);
                cp_async16(base + 2 * ATB + B_TYPE_B + b_so[it], blg + b_src[it] + k0);
            }
        }
        CP_COMMIT();
    };

    wmma::fragment<wmma::accumulator, 16, 16, 16, float> c[MI][2];
#pragma unroll
    for (int mi = 0; mi < MI; mi++)
#pragma unroll
        for (int ni = 0; ni < 2; ni++) wmma::fill_fragment(c[mi][ni], 0.f);

    issue(0, 0);
    issue(1, 1);

    for (int i = 0; i < NC; i++) {
        CP_WAIT1();
        __syncthreads();
        int buf = i & 1;
        const bf16* sAh = (const bf16*)(smem + buf * STG);
        const bf16* sAl = (const bf16*)(smem + buf * STG + ATB);
        const bf16* sBh = (const bf16*)(smem + buf * STG + 2 * ATB);
        const bf16* sBl = (const bf16*)(smem + buf * STG + 2 * ATB + B_TYPE_B);
#pragma unroll
        for (int kk = 0; kk < 4; kk++) {
            wmma::fragment<wmma::matrix_a, 16, 16, 16, bf16, wmma::row_major> ah[MI], al[MI];
#pragma unroll
            for (int mi = 0; mi < MI; mi++) {
                wmma::load_matrix_sync(ah[mi], sAh + (wm * (BMT / 2) + mi * 16) * LDT + kk * 16, LDT);
                wmma::load_matrix_sync(al[mi], sAl + (wm * (BMT / 2) + mi * 16) * LDT + kk * 16, LDT);
            }
#pragma unroll
            for (int ni = 0; ni < 2; ni++) {
                wmma::fragment<wmma::matrix_b, 16, 16, 16, bf16, wmma::col_major> bhf, blf;
                wmma::load_matrix_sync(bhf, sBh + (wn * 32 + ni * 16) * LDT + kk * 16, LDT);
                wmma::load_matrix_sync(blf, sBl + (wn * 32 + ni * 16) * LDT + kk * 16, LDT);
#pragma unroll
                for (int mi = 0; mi < MI; mi++) {
                    wmma::mma_sync(c[mi][ni], ah[mi], bhf, c[mi][ni]);
                    wmma::mma_sync(c[mi][ni], ah[mi], blf, c[mi][ni]);
                    wmma::mma_sync(c[mi][ni], al[mi], bhf, c[mi][ni]);
                }
            }
        }
        __syncthreads();
        issue(i + 2, buf);
    }

    // ---- epilogue: NPASS 64-row passes through smem ----
    float* sC = (float*)smem;
    int lrow = tid >> 3;             // 0..63
    int cseg = (tid & 7) * 32;       // 32-col segment
#pragma unroll
    for (int pass = 0; pass < NPASS; pass++) {
        __syncthreads();
        if ((wm * (BMT / 2)) / 64 == pass) {
            int rbase = (wm * (BMT / 2)) % 64;
#pragma unroll
            for (int mi = 0; mi < MI; mi++)
#pragma unroll
                for (int ni = 0; ni < 2; ni++)
                    wmma::store_matrix_sync(sC + (rbase + mi * 16) * CLD + wn * 32 + ni * 16,
                                            c[mi][ni], CLD, wmma::mem_row_major);
        }
        __syncthreads();
        int arow = by * BMT + pass * 64 + lrow;
        if (arow >= Mrows) continue;
        const float* src = sC + lrow * CLD + cseg;
        int colb = bx * BNw + cseg;
        if (MODE == 2) {
            int p = list[arow];
            size_t ro = (size_t)p * DFFc + colb;
#pragma unroll
            for (int j = 0; j < 16; j++) {
                float v0 = src[2 * j], v1 = src[2 * j + 1];
                v0 = v0 / (1.f + expf(-v0));
                v1 = v1 / (1.f + expf(-v1));
                bf16 h0 = __float2bfloat16_rn(v0);
                bf16 h1 = __float2bfloat16_rn(v1);
                __nv_bfloat162 hv; hv.x = h0; hv.y = h1;
                __nv_bfloat162 lv;
                lv.x = __float2bfloat16_rn(v0 - __bfloat162float(h0));
                lv.y = __float2bfloat16_rn(v1 - __bfloat162float(h1));
                *((__nv_bfloat162*)(Chh + ro) + j) = hv;
                *((__nv_bfloat162*)(Chl + ro) + j) = lv;
            }
        } else if (MODE == 3) {
            int p = list[arow];
            float gate = g_gate[p];
            size_t ro = (size_t)p * DM + colb;
#pragma unroll
            for (int j = 0; j < 8; j++) {
                float4 v = *(const float4*)(src + 4 * j);
                v.x *= gate; v.y *= gate; v.z *= gate; v.w *= gate;
                *(float4*)(Cf + ro + 4 * j) = v;
            }
        } else {
            size_t ro = (size_t)arow * N + colb;
#pragma unroll
            for (int j = 0; j < 8; j++) {
                float4 v = *(const float4*)(src + 4 * j);
                if (MODE == 1) {
                    float4 rs = *(const float4*)(resid + ro + 4 * j);
                    v.x += rs.x; v.y += rs.y; v.z += rs.z; v.w += rs.w;
                }
                *(float4*)(cf + ro + 4 * j) = v;
            }
        }
    }
}

// ---------------- finalize ----------------
__global__ void finalize_k(float* __restrict__ out, int out_size) {
    int t = blockIdx.x;
    for (int i = threadIdx.x; i < DM; i += 256) {
        size_t o = (size_t)t * DM + i;
        out[o] = g_x1[o] + g_moe[(size_t)(2 * t) * DM + i] + g_moe[(size_t)(2 * t + 1) * DM + i];
    }
    if (blockIdx.x == 0 && threadIdx.x == 0 && out_size > TT * DM) {
        float aux = 0.f;
        for (int e = 0; e < EE; e++)
            aux += ((float)g_cnt[e] / (float)(TT * 2)) * (g_pmean[e] / (float)TT);
        out[out_size - 1] = aux * (float)EE;
    }
}

// ---------------- host launcher ----------------
extern "C" void kernel_launch(void* const* d_in, const int* in_sizes, int n_in,
                              void* d_out, int out_size) {
    const float* x     = (const float*)d_in[0];
    const float* n1w   = (const float*)d_in[2];
    const float* n2w   = (const float*)d_in[3];
    const float* Wr    = (const float*)d_in[4];
    const float* Wk    = (const float*)d_in[5];
    const float* Wv    = (const float*)d_in[6];
    const float* Wo    = (const float*)d_in[7];
    const float* decay = (const float*)d_in[8];
    const float* bonus = (const float*)d_in[9];
    const float* rw    = (const float*)d_in[10];
    const float* w1    = (const float*)d_in[11];
    const float* w2    = (const float*)d_in[12];
    float* out = (float*)d_out;

    float *rkv, *yf, *yb, *x1, *xn2, *moe;
    bf16 *xn1h, *xn1l, *yah, *yal, *xn2h, *xn2l, *hh, *hl;
    bf16 *wqkvh, *wqkvl, *woh, *wol, *w1h, *w1l, *w2h, *w2l;
    cudaGetSymbolAddress((void**)&rkv,  g_rkv);
    cudaGetSymbolAddress((void**)&yf,   g_yf);
    cudaGetSymbolAddress((void**)&yb,   g_yb);
    cudaGetSymbolAddress((void**)&x1,   g_x1);
    cudaGetSymbolAddress((void**)&xn2,  g_xn2);
    cudaGetSymbolAddress((void**)&moe,  g_moe);
    cudaGetSymbolAddress((void**)&xn1h, g_xn1h);
    cudaGetSymbolAddress((void**)&xn1l, g_xn1l);
    cudaGetSymbolAddress((void**)&yah,  g_yah);
    cudaGetSymbolAddress((void**)&yal,  g_yal);
    cudaGetSymbolAddress((void**)&xn2h, g_xn2h);
    cudaGetSymbolAddress((void**)&xn2l, g_xn2l);
    cudaGetSymbolAddress((void**)&hh,   g_hh);
    cudaGetSymbolAddress((void**)&hl,   g_hl);
    cudaGetSymbolAddress((void**)&wqkvh, g_wqkvh);
    cudaGetSymbolAddress((void**)&wqkvl, g_wqkvl);
    cudaGetSymbolAddress((void**)&woh,  g_woh);
    cudaGetSymbolAddress((void**)&wol,  g_wol);
    cudaGetSymbolAddress((void**)&w1h,  g_w1h);
    cudaGetSymbolAddress((void**)&w1l,  g_w1l);
    cudaGetSymbolAddress((void**)&w2h,  g_w2h);
    cudaGetSymbolAddress((void**)&w2l,  g_w2l);

    cudaFuncSetAttribute(wgemm_k<0, 128>, cudaFuncAttributeMaxDynamicSharedMemorySize, GCfg<128>::SMEM);
    cudaFuncSetAttribute(wgemm_k<1, 64>,  cudaFuncAttributeMaxDynamicSharedMemorySize, GCfg<64>::SMEM);
    cudaFuncSetAttribute(wgemm_k<2, 128>, cudaFuncAttributeMaxDynamicSharedMemorySize, GCfg<128>::SMEM);
    cudaFuncSetAttribute(wgemm_k<3, 128>, cudaFuncAttributeMaxDynamicSharedMemorySize, GCfg<128>::SMEM);

    zero_k<<<1, 32>>>();                                                   // 1

    dim3 tb(32, 8);
    tsplit_k<<<dim3(DM / 32, DM / 32, 1), tb>>>(Wr, wqkvh,               wqkvl,               DM, DM); // 2
    tsplit_k<<<dim3(DM / 32, DM / 32, 1), tb>>>(Wk, wqkvh + DM * DM,     wqkvl + DM * DM,     DM, DM); // 3
    tsplit_k<<<dim3(DM / 32, DM / 32, 1), tb>>>(Wv, wqkvh + 2 * DM * DM, wqkvl + 2 * DM * DM, DM, DM); // 4

    rmsnorm_k<false><<<TT, 256>>>(x, n1w, nullptr, xn1h, xn1l);            // 5

    // QKV — 6th launch
    wgemm_k<0, 128><<<dim3(DM / BNw, TT / 128, 3), NT, GCfg<128>::SMEM>>>(
        xn1h, xn1l, wqkvh, wqkvl, nullptr, rkv, nullptr, nullptr, TT, DM, DM);

    scan_k<<<dim3(HH * 2, BB, 2), 128>>>(rkv, rkv + TT * DM, rkv + 2 * TT * DM, decay, bonus);

    tsplit_k<<<dim3(DM / 32, DM / 32, 1), tb>>>(Wo, woh, wol, DM, DM);

    splitadd_k<<<(TT * DM + 255) / 256, 256>>>(yf, yb, yah, yal, TT * DM);

    // x1 = x + (yf+yb) @ Wo
    wgemm_k<1, 64><<<dim3(DM / BNw, TT / 64, 1), NT, GCfg<64>::SMEM>>>(
        yah, yal, woh, wol, x, x1, nullptr, nullptr, TT, DM, DM);

    rmsnorm_k<true><<<TT, 256>>>(x1, n2w, xn2, xn2h, xn2l);
    router_k<<<TT, 256>>>(xn2, rw);

    tsplit_k<<<dim3(DFFc / 32, DM / 32, EE), tb>>>(w1, w1h, w1l, DM, DFFc);

    // MoE up
    wgemm_k<2, 128><<<dim3(DFFc / BNw, TT / 128, EE), NT, GCfg<128>::SMEM>>>(
        xn2h, xn2l, w1h, w1l, nullptr, nullptr, hh, hl, 0, DFFc, DM);

    tsplit_k<<<dim3(DM / 32, DFFc / 32, EE), tb>>>(w2, w2h, w2l, DFFc, DM);

    // MoE down
    wgemm_k<3, 128><<<dim3(DM / BNw, TT / 128, EE), NT, GCfg<128>::SMEM>>>(
        hh, hl, w2h, w2l, nullptr, moe, nullptr, nullptr, 0, DM, DFFc);

    finalize_k<<<TT, 256>>>(out, out_size);
}

// round 13
// speedup vs baseline: 1.3136x; 1.3136x over previous
#include <cuda_runtime.h>
#include <cuda_bf16.h>
#include <mma.h>
#include <math.h>
#include <stdint.h>

using namespace nvcuda;

// Problem constants
#define TT   4096
#define DM   1024
#define HH   16
#define HD   64
#define DFFc 2048
#define EE   8
#define SS   2048
#define BB   2

typedef __nv_bfloat16 bf16;

// ---------------- scratch ----------------
__device__ float g_rkv[3 * TT * DM];
__device__ float g_yf[TT * DM];
__device__ float g_yb[TT * DM];
__device__ float g_x1[TT * DM];
__device__ float g_xn2[TT * DM];
__device__ float g_moe[2 * TT * DM];
__device__ bf16  g_xn1h[TT * DM],  g_xn1l[TT * DM];
__device__ bf16  g_yah[TT * DM],   g_yal[TT * DM];
__device__ bf16  g_xn2h[TT * DM],  g_xn2l[TT * DM];
__device__ bf16  g_hh[2 * TT * DFFc], g_hl[2 * TT * DFFc];
__device__ bf16  g_wqkvh[3 * DM * DM], g_wqkvl[3 * DM * DM];
__device__ bf16  g_woh[DM * DM],   g_wol[DM * DM];
__device__ bf16  g_w1h[EE * DFFc * DM], g_w1l[EE * DFFc * DM];
__device__ bf16  g_w2h[EE * DM * DFFc], g_w2l[EE * DM * DFFc];
__device__ float g_gate[2 * TT];
__device__ int   g_list[EE * TT];
__device__ int   g_cnt[EE];
__device__ float g_pmean[EE];

__device__ __forceinline__ uint32_t smem_u32(const void* p) {
    uint32_t a;
    asm("{ .reg .u64 t; cvta.to.shared.u64 t, %1; cvt.u32.u64 %0, t; }" : "=r"(a) : "l"(p));
    return a;
}
__device__ __forceinline__ void cp_async16(uint32_t s, const void* g) {
    asm volatile("cp.async.cg.shared.global [%0], [%1], 16;" :: "r"(s), "l"(g) : "memory");
}
#define CP_COMMIT() asm volatile("cp.async.commit_group;" ::: "memory")
#define CP_WAIT1()  asm volatile("cp.async.wait_group 1;"  ::: "memory")
#define CP_WAIT2()  asm volatile("cp.async.wait_group 2;"  ::: "memory")

// ---------------- small kernels ----------------
__global__ void zero_k() {
    int i = threadIdx.x;
    if (i < EE) { g_cnt[i] = 0; g_pmean[i] = 0.f; }
}

// transpose + split: src [K,N] fp32 (batch z) -> dh/dl [N,K] bf16 (vectorized stores)
__global__ void tsplit_k(const float* __restrict__ src, bf16* __restrict__ dh,
                         bf16* __restrict__ dl, int K, int N) {
    int e = blockIdx.z;
    src += (size_t)e * K * N;
    dh  += (size_t)e * N * K;
    dl  += (size_t)e * N * K;
    __shared__ float tile[32][33];
    int n0 = blockIdx.x * 32, k0 = blockIdx.y * 32;
    int tx = threadIdx.x, ty = threadIdx.y;
#pragma unroll
    for (int i = 0; i < 4; i++)
        tile[ty + i * 8][tx] = src[(size_t)(k0 + ty + i * 8) * N + n0 + tx];
    __syncthreads();
    int t = ty * 32 + tx;
#pragma unroll
    for (int it = 0; it < 2; it++) {
        int i = t + it * 256;
        int row = i >> 4;
        int kp  = i & 15;
        float v0 = tile[kp * 2][row];
        float v1 = tile[kp * 2 + 1][row];
        bf16 h0 = __float2bfloat16_rn(v0);
        bf16 h1 = __float2bfloat16_rn(v1);
        __nv_bfloat162 hv; hv.x = h0; hv.y = h1;
        __nv_bfloat162 lv;
        lv.x = __float2bfloat16_rn(v0 - __bfloat162float(h0));
        lv.y = __float2bfloat16_rn(v1 - __bfloat162float(h1));
        size_t o = ((size_t)(n0 + row) * K + k0 + kp * 2) >> 1;
        ((__nv_bfloat162*)dh)[o] = hv;
        ((__nv_bfloat162*)dl)[o] = lv;
    }
}

__global__ void splitadd_k(const float* __restrict__ a, const float* __restrict__ b,
                           bf16* __restrict__ hi, bf16* __restrict__ lo, int n) {
    int i = blockIdx.x * blockDim.x + threadIdx.x;
    if (i >= n) return;
    float v = a[i] + b[i];
    bf16 h = __float2bfloat16_rn(v);
    hi[i] = h;
    lo[i] = __float2bfloat16_rn(v - __bfloat162float(h));
}

template <bool WRITE_F32>
__global__ void rmsnorm_k(const float* __restrict__ x, const float* __restrict__ w,
                          float* __restrict__ ofp, bf16* __restrict__ ohi, bf16* __restrict__ olo) {
    int t = blockIdx.x;
    const float* xr = x + (size_t)t * DM;
    float s = 0.f;
    for (int i = threadIdx.x; i < DM; i += 256) { float v = xr[i]; s += v * v; }
    for (int off = 16; off; off >>= 1) s += __shfl_xor_sync(0xffffffffu, s, off);
    __shared__ float red[8];
    int wrp = threadIdx.x >> 5, ln = threadIdx.x & 31;
    if (ln == 0) red[wrp] = s;
    __syncthreads();
    if (wrp == 0) {
        float v = (ln < 8) ? red[ln] : 0.f;
        for (int off = 4; off; off >>= 1) v += __shfl_xor_sync(0xffffffffu, v, off);
        if (ln == 0) red[0] = v;
    }
    __syncthreads();
    float scale = rsqrtf(red[0] / (float)DM + 1e-6f);
    size_t base = (size_t)t * DM;
    for (int i = threadIdx.x; i < DM; i += 256) {
        float v = xr[i] * scale * w[i];
        if (WRITE_F32) ofp[base + i] = v;
        bf16 h = __float2bfloat16_rn(v);
        ohi[base + i] = h;
        olo[base + i] = __float2bfloat16_rn(v - __bfloat162float(h));
    }
}

// ---------------- RWKV bidirectional scan, 4-stage cp.async pipeline ----------------
// grid: (H*2, B, 2dirs); block 128. Threads 0-39 feed the pipeline (16B each):
//   0-15: r row (64 floats), 16-31: k row (64 floats), 32-39: v half (32 floats).
__global__ void scan_k(const float* __restrict__ r, const float* __restrict__ k,
                       const float* __restrict__ v,
                       const float* __restrict__ decay, const float* __restrict__ bonus) {
    int h  = blockIdx.x >> 1;
    int vh = blockIdx.x & 1;
    int b  = blockIdx.y;
    int dir = blockIdx.z;
    int tid = threadIdx.x;
    int vcol  = vh * 32 + (tid >> 2);
    int kc    = tid & 3;
    int kbase = kc * 16;

    float Sst[16], wr_[16], ur_[16];
#pragma unroll
    for (int i = 0; i < 16; i++) {
        Sst[i] = 0.f;
        float d = decay[h * HD + kbase + i];
        wr_[i] = expf(-expf(d));
        ur_[i] = bonus[h * HD + kbase + i];
    }
    float* yo = dir ? g_yb : g_yf;

    // smem: r[4][64] | k[4][64] | v[4][32]
    __shared__ float sbuf[4 * 64 + 4 * 64 + 4 * 32];
    float* s_r = sbuf;
    float* s_k = sbuf + 256;
    float* s_v = sbuf + 512;
    uint32_t sb = smem_u32(sbuf);

    auto sidx = [&](int s) -> size_t {
        int idx = dir ? (SS - 1 - s) : s;
        return ((size_t)(b * SS + idx)) * DM + h * HD;
    };

    auto issue = [&](int s) {
        if (s < SS) {
            size_t base = sidx(s);
            int st = s & 3;
            if (tid < 16)
                cp_async16(sb + (uint32_t)(st * 64 + tid * 4) * 4, r + base + tid * 4);
            else if (tid < 32)
                cp_async16(sb + (uint32_t)(256 + st * 64 + (tid - 16) * 4) * 4, k + base + (tid - 16) * 4);
            else if (tid < 40)
                cp_async16(sb + (uint32_t)(512 + st * 32 + (tid - 32) * 4) * 4, v + base + vh * 32 + (tid - 32) * 4);
        }
        CP_COMMIT();
    };

    issue(0); issue(1); issue(2);

    int vloc = tid >> 2;
    for (int s = 0; s < SS; s++) {
        CP_WAIT2();
        __syncthreads();
        int st = s & 3;
        float vv = s_v[st * 32 + vloc];
        const float* kr = s_k + st * 64 + kbase;
        const float* rp = s_r + st * 64 + kbase;
        float y = 0.f;
#pragma unroll
        for (int i = 0; i < 16; i++) {
            float kk  = kr[i];
            float rv  = rp[i];
            float kv  = kk * vv;
            float tmp = fmaf(ur_[i], kv, Sst[i]);
            y = fmaf(rv, tmp, y);
            Sst[i] = fmaf(wr_[i], Sst[i], kv);
        }
        y += __shfl_xor_sync(0xffffffffu, y, 1);
        y += __shfl_xor_sync(0xffffffffu, y, 2);
        if (kc == 0) yo[sidx(s) + vcol] = y;
        issue(s + 3);
    }
}

// ---------------- router ----------------
__global__ void router_k(const float* __restrict__ xn2, const float* __restrict__ rw) {
    int t = blockIdx.x, tid = threadIdx.x;
    __shared__ float sx[DM];
    __shared__ float slog[8];
    const float* xr = xn2 + (size_t)t * DM;
    for (int i = tid; i < DM; i += 256) sx[i] = xr[i];
    __syncthreads();
    int w = tid >> 5, l = tid & 31;
    float acc = 0.f;
    for (int d = l; d < DM; d += 32) acc = fmaf(sx[d], rw[d * EE + w], acc);
    for (int off = 16; off; off >>= 1) acc += __shfl_xor_sync(0xffffffffu, acc, off);
    if (l == 0) slog[w] = acc;
    __syncthreads();
    if (tid == 0) {
        float mx = -1e30f;
        for (int e = 0; e < EE; e++) mx = fmaxf(mx, slog[e]);
        float p[EE], sum = 0.f;
        for (int e = 0; e < EE; e++) { p[e] = expf(slog[e] - mx); sum += p[e]; }
        float inv = 1.f / sum;
        int e0 = 0; float b0 = -1.f;
        for (int e = 0; e < EE; e++) { p[e] *= inv; if (p[e] > b0) { b0 = p[e]; e0 = e; } }
        int e1 = -1; float b1 = -1.f;
        for (int e = 0; e < EE; e++) { if (e == e0) continue; if (p[e] > b1) { b1 = p[e]; e1 = e; } }
        float gs = 1.f / (b0 + b1);
        g_gate[2 * t]     = b0 * gs;
        g_gate[2 * t + 1] = b1 * gs;
        int pos0 = atomicAdd(&g_cnt[e0], 1); g_list[e0 * TT + pos0] = 2 * t;
        int pos1 = atomicAdd(&g_cnt[e1], 1); g_list[e1 * TT + pos1] = 2 * t + 1;
        for (int e = 0; e < EE; e++) atomicAdd(&g_pmean[e], p[e]);
    }
}

// ---------------- WMMA bf16 split GEMM, 2-stage cp.async, BK=64 (R10 config) ----------------
// CTA tile BMT x 256, BK=64, 8 warps (2M x 4N), warp tile (BMT/2) x 64.
// D = Ah*Bh + Ah*Bl + Al*Bh   (fp32 accumulate)
#define BNw 256
#define BKw 64
#define LDT 72
#define B_TYPE_B  (256 * LDT * 2)          // 36864 bytes
#define CLD 260                            // epilogue fp32 ld

template <int BMT> struct GCfg {
    static constexpr int ATB   = BMT * LDT * 2;
    static constexpr int STAGE = 2 * ATB + 2 * B_TYPE_B;
    static constexpr int SMEM  = 2 * STAGE;
};

template <int MODE, int BMT>
__global__ void __launch_bounds__(256, 1)
wgemm_k(const bf16* __restrict__ Ah, const bf16* __restrict__ Al,
        const bf16* __restrict__ Bh, const bf16* __restrict__ Bl,
        const float* __restrict__ resid, float* __restrict__ Cf,
        bf16* __restrict__ Chh, bf16* __restrict__ Chl,
        int M, int N, int K) {
    constexpr int MI   = BMT / 32;
    constexpr int AITS = BMT / 32;
    constexpr int ATB  = GCfg<BMT>::ATB;
    constexpr int STG  = GCfg<BMT>::STAGE;
    constexpr int NPASS = BMT / 64;

    int z = blockIdx.z;
    int bx = blockIdx.x, by = blockIdx.y;
    int Mrows = M;
    const int* list = nullptr;
    if (MODE == 2 || MODE == 3) { Mrows = g_cnt[z]; list = g_list + z * TT; }
    if (by * BMT >= Mrows) return;

    size_t boff = 0;
    if (MODE == 0) boff = (size_t)z * DM * DM;
    if (MODE == 2) boff = (size_t)z * DFFc * DM;
    if (MODE == 3) boff = (size_t)z * DM * DFFc;
    const bf16* bhg = Bh + boff;
    const bf16* blg = Bl + boff;
    float* cf = Cf;
    if (MODE == 0) cf = Cf + (size_t)z * TT * DM;

    extern __shared__ char smem[];
    uint32_t sb = smem_u32(smem);

    int tid = threadIdx.x;
    int wid = tid >> 5;
    int wm = wid & 1;
    int wn = wid >> 1;

    size_t a_src[AITS]; uint32_t a_so[AITS];
#pragma unroll
    for (int it = 0; it < AITS; it++) {
        int idx = tid + it * 256;
        int row = idx >> 3, seg = idx & 7;
        int ar = by * BMT + row;
        if (MODE == 2 || MODE == 3) {
            int rc = ar < Mrows ? ar : (Mrows - 1);
            int p = list[rc];
            ar = (MODE == 2) ? (p >> 1) : p;
        }
        a_src[it] = (size_t)ar * K + seg * 8;
        a_so[it] = (uint32_t)((row * LDT + seg * 8) * 2);
    }
    size_t b_src[8]; uint32_t b_so[8];
#pragma unroll
    for (int it = 0; it < 8; it++) {
        int idx = tid + it * 256;
        int row = idx >> 3, seg = idx & 7;
        b_src[it] = (size_t)(bx * BNw + row) * K + seg * 8;
        b_so[it] = (uint32_t)((row * LDT + seg * 8) * 2);
    }

    const int NC = K / BKw;
    auto issue = [&](int ci, int buf) {
        if (ci < NC) {
            int k0 = ci * BKw;
            uint32_t base = sb + buf * STG;
#pragma unroll
            for (int it = 0; it < AITS; it++) {
                cp_async16(base + a_so[it],       Ah + a_src[it] + k0);
                cp_async16(base + ATB + a_so[it], Al + a_src[it] + k0);
            }
#pragma unroll
            for (int it = 0; it < 8; it++) {
                cp_async16(base + 2 * ATB + b_so[it],            bhg + b_src[it] + k0);
                cp_async16(base + 2 * ATB + B_TYPE_B + b_so[it], blg + b_src[it] + k0);
            }
        }
        CP_COMMIT();
    };

    wmma::fragment<wmma::accumulator, 16, 16, 16, float> c[MI][4];
#pragma unroll
    for (int mi = 0; mi < MI; mi++)
#pragma unroll
        for (int ni = 0; ni < 4; ni++) wmma::fill_fragment(c[mi][ni], 0.f);

    issue(0, 0);
    issue(1, 1);

    for (int i = 0; i < NC; i++) {
        CP_WAIT1();
        __syncthreads();
        int buf = i & 1;
        const bf16* sAh = (const bf16*)(smem + buf * STG);
        const bf16* sAl = (const bf16*)(smem + buf * STG + ATB);
        const bf16* sBh = (const bf16*)(smem + buf * STG + 2 * ATB);
        const bf16* sBl = (const bf16*)(smem + buf * STG + 2 * ATB + B_TYPE_B);
#pragma unroll
        for (int kk = 0; kk < 4; kk++) {
            wmma::fragment<wmma::matrix_a, 16, 16, 16, bf16, wmma::row_major> ah[MI], al[MI];
#pragma unroll
            for (int mi = 0; mi < MI; mi++) {
                wmma::load_matrix_sync(ah[mi], sAh + (wm * (BMT / 2) + mi * 16) * LDT + kk * 16, LDT);
                wmma::load_matrix_sync(al[mi], sAl + (wm * (BMT / 2) + mi * 16) * LDT + kk * 16, LDT);
            }
#pragma unroll
            for (int ni = 0; ni < 4; ni++) {
                wmma::fragment<wmma::matrix_b, 16, 16, 16, bf16, wmma::col_major> bhf, blf;
                wmma::load_matrix_sync(bhf, sBh + (wn * 64 + ni * 16) * LDT + kk * 16, LDT);
                wmma::load_matrix_sync(blf, sBl + (wn * 64 + ni * 16) * LDT + kk * 16, LDT);
#pragma unroll
                for (int mi = 0; mi < MI; mi++) {
                    wmma::mma_sync(c[mi][ni], ah[mi], bhf, c[mi][ni]);
                    wmma::mma_sync(c[mi][ni], ah[mi], blf, c[mi][ni]);
                    wmma::mma_sync(c[mi][ni], al[mi], bhf, c[mi][ni]);
                }
            }
        }
        __syncthreads();
        issue(i + 2, buf);
    }

    // ---- epilogue: NPASS 64-row passes through smem ----
    float* sC = (float*)smem;
    int lrow = tid >> 2;
    int cseg = (tid & 3) * 64;
#pragma unroll
    for (int pass = 0; pass < NPASS; pass++) {
        __syncthreads();
        if ((wm * (BMT / 2)) / 64 == pass) {
            int rbase = (wm * (BMT / 2)) % 64;
#pragma unroll
            for (int mi = 0; mi < MI; mi++)
#pragma unroll
                for (int ni = 0; ni < 4; ni++)
                    wmma::store_matrix_sync(sC + (rbase + mi * 16) * CLD + wn * 64 + ni * 16,
                                            c[mi][ni], CLD, wmma::mem_row_major);
        }
        __syncthreads();
        int arow = by * BMT + pass * 64 + lrow;
        if (arow >= Mrows) continue;
        const float* src = sC + lrow * CLD + cseg;
        int colb = bx * BNw + cseg;
        if (MODE == 2) {
            int p = list[arow];
            size_t ro = (size_t)p * DFFc + colb;
#pragma unroll
            for (int j = 0; j < 32; j++) {
                float v0 = src[2 * j], v1 = src[2 * j + 1];
                v0 = v0 / (1.f + expf(-v0));
                v1 = v1 / (1.f + expf(-v1));
                bf16 h0 = __float2bfloat16_rn(v0);
                bf16 h1 = __float2bfloat16_rn(v1);
                __nv_bfloat162 hv; hv.x = h0; hv.y = h1;
                __nv_bfloat162 lv;
                lv.x = __float2bfloat16_rn(v0 - __bfloat162float(h0));
                lv.y = __float2bfloat16_rn(v1 - __bfloat162float(h1));
                *((__nv_bfloat162*)(Chh + ro) + j) = hv;
                *((__nv_bfloat162*)(Chl + ro) + j) = lv;
            }
        } else if (MODE == 3) {
            int p = list[arow];
            float gate = g_gate[p];
            size_t ro = (size_t)p * DM + colb;
#pragma unroll
            for (int j = 0; j < 16; j++) {
                float4 v = *(const float4*)(src + 4 * j);
                v.x *= gate; v.y *= gate; v.z *= gate; v.w *= gate;
                *(float4*)(Cf + ro + 4 * j) = v;
            }
        } else {
            size_t ro = (size_t)arow * N + colb;
#pragma unroll
            for (int j = 0; j < 16; j++) {
                float4 v = *(const float4*)(src + 4 * j);
                if (MODE == 1) {
                    float4 rs = *(const float4*)(resid + ro + 4 * j);
                    v.x += rs.x; v.y += rs.y; v.z += rs.z; v.w += rs.w;
                }
                *(float4*)(cf + ro + 4 * j) = v;
            }
        }
    }
}

// ---------------- finalize ----------------
__global__ void finalize_k(float* __restrict__ out, int out_size) {
    int t = blockIdx.x;
    for (int i = threadIdx.x; i < DM; i += 256) {
        size_t o = (size_t)t * DM + i;
        out[o] = g_x1[o] + g_moe[(size_t)(2 * t) * DM + i] + g_moe[(size_t)(2 * t + 1) * DM + i];
    }
    if (blockIdx.x == 0 && threadIdx.x == 0 && out_size > TT * DM) {
        float aux = 0.f;
        for (int e = 0; e < EE; e++)
            aux += ((float)g_cnt[e] / (float)(TT * 2)) * (g_pmean[e] / (float)TT);
        out[out_size - 1] = aux * (float)EE;
    }
}

// ---------------- host launcher ----------------
extern "C" void kernel_launch(void* const* d_in, const int* in_sizes, int n_in,
                              void* d_out, int out_size) {
    const float* x     = (const float*)d_in[0];
    const float* n1w   = (const float*)d_in[2];
    const float* n2w   = (const float*)d_in[3];
    const float* Wr    = (const float*)d_in[4];
    const float* Wk    = (const float*)d_in[5];
    const float* Wv    = (const float*)d_in[6];
    const float* Wo    = (const float*)d_in[7];
    const float* decay = (const float*)d_in[8];
    const float* bonus = (const float*)d_in[9];
    const float* rw    = (const float*)d_in[10];
    const float* w1    = (const float*)d_in[11];
    const float* w2    = (const float*)d_in[12];
    float* out = (float*)d_out;

    float *rkv, *yf, *yb, *x1, *xn2, *moe;
    bf16 *xn1h, *xn1l, *yah, *yal, *xn2h, *xn2l, *hh, *hl;
    bf16 *wqkvh, *wqkvl, *woh, *wol, *w1h, *w1l, *w2h, *w2l;
    cudaGetSymbolAddress((void**)&rkv,  g_rkv);
    cudaGetSymbolAddress((void**)&yf,   g_yf);
    cudaGetSymbolAddress((void**)&yb,   g_yb);
    cudaGetSymbolAddress((void**)&x1,   g_x1);
    cudaGetSymbolAddress((void**)&xn2,  g_xn2);
    cudaGetSymbolAddress((void**)&moe,  g_moe);
    cudaGetSymbolAddress((void**)&xn1h, g_xn1h);
    cudaGetSymbolAddress((void**)&xn1l, g_xn1l);
    cudaGetSymbolAddress((void**)&yah,  g_yah);
    cudaGetSymbolAddress((void**)&yal,  g_yal);
    cudaGetSymbolAddress((void**)&xn2h, g_xn2h);
    cudaGetSymbolAddress((void**)&xn2l, g_xn2l);
    cudaGetSymbolAddress((void**)&hh,   g_hh);
    cudaGetSymbolAddress((void**)&hl,   g_hl);
    cudaGetSymbolAddress((void**)&wqkvh, g_wqkvh);
    cudaGetSymbolAddress((void**)&wqkvl, g_wqkvl);
    cudaGetSymbolAddress((void**)&woh,  g_woh);
    cudaGetSymbolAddress((void**)&wol,  g_wol);
    cudaGetSymbolAddress((void**)&w1h,  g_w1h);
    cudaGetSymbolAddress((void**)&w1l,  g_w1l);
    cudaGetSymbolAddress((void**)&w2h,  g_w2h);
    cudaGetSymbolAddress((void**)&w2l,  g_w2l);

    cudaFuncSetAttribute(wgemm_k<0, 128>, cudaFuncAttributeMaxDynamicSharedMemorySize, GCfg<128>::SMEM);
    cudaFuncSetAttribute(wgemm_k<1, 64>,  cudaFuncAttributeMaxDynamicSharedMemorySize, GCfg<64>::SMEM);
    cudaFuncSetAttribute(wgemm_k<2, 128>, cudaFuncAttributeMaxDynamicSharedMemorySize, GCfg<128>::SMEM);
    cudaFuncSetAttribute(wgemm_k<3, 128>, cudaFuncAttributeMaxDynamicSharedMemorySize, GCfg<128>::SMEM);

    zero_k<<<1, 32>>>();

    dim3 tb(32, 8);
    tsplit_k<<<dim3(DM / 32, DM / 32, 1), tb>>>(Wr, wqkvh,               wqkvl,               DM, DM);
    tsplit_k<<<dim3(DM / 32, DM / 32, 1), tb>>>(Wk, wqkvh + DM * DM,     wqkvl + DM * DM,     DM, DM);
    tsplit_k<<<dim3(DM / 32, DM / 32, 1), tb>>>(Wv, wqkvh + 2 * DM * DM, wqkvl + 2 * DM * DM, DM, DM);

    rmsnorm_k<false><<<TT, 256>>>(x, n1w, nullptr, xn1h, xn1l);

    // QKV
    wgemm_k<0, 128><<<dim3(DM / BNw, TT / 128, 3), 256, GCfg<128>::SMEM>>>(
        xn1h, xn1l, wqkvh, wqkvl, nullptr, rkv, nullptr, nullptr, TT, DM, DM);

    scan_k<<<dim3(HH * 2, BB, 2), 128>>>(rkv, rkv + TT * DM, rkv + 2 * TT * DM, decay, bonus);

    tsplit_k<<<dim3(DM / 32, DM / 32, 1), tb>>>(Wo, woh, wol, DM, DM);

    splitadd_k<<<(TT * DM + 255) / 256, 256>>>(yf, yb, yah, yal, TT * DM);

    // x1 = x + (yf+yb) @ Wo
    wgemm_k<1, 64><<<dim3(DM / BNw, TT / 64, 1), 256, GCfg<64>::SMEM>>>(
        yah, yal, woh, wol, x, x1, nullptr, nullptr, TT, DM, DM);

    rmsnorm_k<true><<<TT, 256>>>(x1, n2w, xn2, xn2h, xn2l);
    router_k<<<TT, 256>>>(xn2, rw);

    tsplit_k<<<dim3(DFFc / 32, DM / 32, EE), tb>>>(w1, w1h, w1l, DM, DFFc);

    // MoE up
    wgemm_k<2, 128><<<dim3(DFFc / BNw, TT / 128, EE), 256, GCfg<128>::SMEM>>>(
        xn2h, xn2l, w1h, w1l, nullptr, nullptr, hh, hl, 0, DFFc, DM);

    tsplit_k<<<dim3(DM / 32, DFFc / 32, EE), tb>>>(w2, w2h, w2l, DFFc, DM);

    // MoE down
    wgemm_k<3, 128><<<dim3(DM / BNw, TT / 128, EE), 256, GCfg<128>::SMEM>>>(
        hh, hl, w2h, w2l, nullptr, moe, nullptr, nullptr, 0, DM, DFFc);

    finalize_k<<<TT, 256>>>(out, out_size);
}

// round 14
// speedup vs baseline: 1.5227x; 1.1592x over previous
#include <cuda_runtime.h>
#include <cuda_bf16.h>
#include <cuda_fp16.h>
#include <mma.h>
#include <math.h>
#include <stdint.h>

using namespace nvcuda;

// Problem constants
#define TT   4096
#define DM   1024
#define HH   16
#define HD   64
#define DFFc 2048
#define EE   8
#define SS   2048
#define BB   2

typedef __nv_bfloat16 bf16;
typedef __half f16;

// ---------------- scratch ----------------
__device__ float g_rkv[3 * TT * DM];
__device__ float g_yf[TT * DM];
__device__ float g_yb[TT * DM];
__device__ float g_x1[TT * DM];
__device__ float g_xn2[TT * DM];
__device__ float g_moe[2 * TT * DM];
__device__ bf16  g_xn1h[TT * DM],  g_xn1l[TT * DM];
__device__ bf16  g_yah[TT * DM],   g_yal[TT * DM];
__device__ f16   g_xn2f[TT * DM];
__device__ f16   g_hf[2 * TT * DFFc];            // 32 MB
__device__ bf16  g_wqkvh[3 * DM * DM], g_wqkvl[3 * DM * DM];
__device__ bf16  g_woh[DM * DM],   g_wol[DM * DM];
__device__ f16   g_w1fh[EE * DFFc * DM], g_w1fl[EE * DFFc * DM];
__device__ f16   g_w2fh[EE * DM * DFFc], g_w2fl[EE * DM * DFFc];
__device__ float g_gate[2 * TT];
__device__ int   g_list[EE * TT];
__device__ int   g_cnt[EE];
__device__ float g_pmean[EE];

__device__ __forceinline__ uint32_t smem_u32(const void* p) {
    uint32_t a;
    asm("{ .reg .u64 t; cvta.to.shared.u64 t, %1; cvt.u32.u64 %0, t; }" : "=r"(a) : "l"(p));
    return a;
}
__device__ __forceinline__ void cp_async16(uint32_t s, const void* g) {
    asm volatile("cp.async.cg.shared.global [%0], [%1], 16;" :: "r"(s), "l"(g) : "memory");
}
#define CP_COMMIT() asm volatile("cp.async.commit_group;" ::: "memory")
#define CP_WAIT1()  asm volatile("cp.async.wait_group 1;"  ::: "memory")
#define CP_WAIT2()  asm volatile("cp.async.wait_group 2;"  ::: "memory")

// ---------------- small kernels ----------------
__global__ void zero_k() {
    int i = threadIdx.x;
    if (i < EE) { g_cnt[i] = 0; g_pmean[i] = 0.f; }
}

// transpose + split bf16: src [K,N] fp32 (batch z) -> dh/dl [N,K] bf16
__global__ void tsplit_k(const float* __restrict__ src, bf16* __restrict__ dh,
                         bf16* __restrict__ dl, int K, int N) {
    int e = blockIdx.z;
    src += (size_t)e * K * N;
    dh  += (size_t)e * N * K;
    dl  += (size_t)e * N * K;
    __shared__ float tile[32][33];
    int n0 = blockIdx.x * 32, k0 = blockIdx.y * 32;
    int tx = threadIdx.x, ty = threadIdx.y;
#pragma unroll
    for (int i = 0; i < 4; i++)
        tile[ty + i * 8][tx] = src[(size_t)(k0 + ty + i * 8) * N + n0 + tx];
    __syncthreads();
    int t = ty * 32 + tx;
#pragma unroll
    for (int it = 0; it < 2; it++) {
        int i = t + it * 256;
        int row = i >> 4;
        int kp  = i & 15;
        float v0 = tile[kp * 2][row];
        float v1 = tile[kp * 2 + 1][row];
        bf16 h0 = __float2bfloat16_rn(v0);
        bf16 h1 = __float2bfloat16_rn(v1);
        __nv_bfloat162 hv; hv.x = h0; hv.y = h1;
        __nv_bfloat162 lv;
        lv.x = __float2bfloat16_rn(v0 - __bfloat162float(h0));
        lv.y = __float2bfloat16_rn(v1 - __bfloat162float(h1));
        size_t o = ((size_t)(n0 + row) * K + k0 + kp * 2) >> 1;
        ((__nv_bfloat162*)dh)[o] = hv;
        ((__nv_bfloat162*)dl)[o] = lv;
    }
}

// transpose + split fp16: src [K,N] fp32 (batch z) -> dh/dl [N,K] fp16
__global__ void tsplit16_k(const float* __restrict__ src, f16* __restrict__ dh,
                           f16* __restrict__ dl, int K, int N) {
    int e = blockIdx.z;
    src += (size_t)e * K * N;
    dh  += (size_t)e * N * K;
    dl  += (size_t)e * N * K;
    __shared__ float tile[32][33];
    int n0 = blockIdx.x * 32, k0 = blockIdx.y * 32;
    int tx = threadIdx.x, ty = threadIdx.y;
#pragma unroll
    for (int i = 0; i < 4; i++)
        tile[ty + i * 8][tx] = src[(size_t)(k0 + ty + i * 8) * N + n0 + tx];
    __syncthreads();
    int t = ty * 32 + tx;
#pragma unroll
    for (int it = 0; it < 2; it++) {
        int i = t + it * 256;
        int row = i >> 4;
        int kp  = i & 15;
        float v0 = tile[kp * 2][row];
        float v1 = tile[kp * 2 + 1][row];
        f16 h0 = __float2half_rn(v0);
        f16 h1 = __float2half_rn(v1);
        __half2 hv; hv.x = h0; hv.y = h1;
        __half2 lv;
        lv.x = __float2half_rn(v0 - __half2float(h0));
        lv.y = __float2half_rn(v1 - __half2float(h1));
        size_t o = ((size_t)(n0 + row) * K + k0 + kp * 2) >> 1;
        ((__half2*)dh)[o] = hv;
        ((__half2*)dl)[o] = lv;
    }
}

__global__ void splitadd_k(const float* __restrict__ a, const float* __restrict__ b,
                           bf16* __restrict__ hi, bf16* __restrict__ lo, int n) {
    int i = blockIdx.x * blockDim.x + threadIdx.x;
    if (i >= n) return;
    float v = a[i] + b[i];
    bf16 h = __float2bfloat16_rn(v);
    hi[i] = h;
    lo[i] = __float2bfloat16_rn(v - __bfloat162float(h));
}

// rmsnorm -> bf16 hi/lo (for QKV)
__global__ void rmsnorm_k(const float* __restrict__ x, const float* __restrict__ w,
                          bf16* __restrict__ ohi, bf16* __restrict__ olo) {
    int t = blockIdx.x;
    const float* xr = x + (size_t)t * DM;
    float s = 0.f;
    for (int i = threadIdx.x; i < DM; i += 256) { float v = xr[i]; s += v * v; }
    for (int off = 16; off; off >>= 1) s += __shfl_xor_sync(0xffffffffu, s, off);
    __shared__ float red[8];
    int wrp = threadIdx.x >> 5, ln = threadIdx.x & 31;
    if (ln == 0) red[wrp] = s;
    __syncthreads();
    if (wrp == 0) {
        float v = (ln < 8) ? red[ln] : 0.f;
        for (int off = 4; off; off >>= 1) v += __shfl_xor_sync(0xffffffffu, v, off);
        if (ln == 0) red[0] = v;
    }
    __syncthreads();
    float scale = rsqrtf(red[0] / (float)DM + 1e-6f);
    size_t base = (size_t)t * DM;
    for (int i = threadIdx.x; i < DM; i += 256) {
        float v = xr[i] * scale * w[i];
        bf16 h = __float2bfloat16_rn(v);
        ohi[base + i] = h;
        olo[base + i] = __float2bfloat16_rn(v - __bfloat162float(h));
    }
}

// rmsnorm -> fp32 (router) + single fp16 (MoE A operand)
__global__ void rmsnorm2_k(const float* __restrict__ x, const float* __restrict__ w,
                           float* __restrict__ ofp, f16* __restrict__ o16) {
    int t = blockIdx.x;
    const float* xr = x + (size_t)t * DM;
    float s = 0.f;
    for (int i = threadIdx.x; i < DM; i += 256) { float v = xr[i]; s += v * v; }
    for (int off = 16; off; off >>= 1) s += __shfl_xor_sync(0xffffffffu, s, off);
    __shared__ float red[8];
    int wrp = threadIdx.x >> 5, ln = threadIdx.x & 31;
    if (ln == 0) red[wrp] = s;
    __syncthreads();
    if (wrp == 0) {
        float v = (ln < 8) ? red[ln] : 0.f;
        for (int off = 4; off; off >>= 1) v += __shfl_xor_sync(0xffffffffu, v, off);
        if (ln == 0) red[0] = v;
    }
    __syncthreads();
    float scale = rsqrtf(red[0] / (float)DM + 1e-6f);
    size_t base = (size_t)t * DM;
    for (int i = threadIdx.x; i < DM; i += 256) {
        float v = xr[i] * scale * w[i];
        ofp[base + i] = v;
        o16[base + i] = __float2half_rn(v);
    }
}

// ---------------- RWKV bidirectional scan, 4-stage cp.async pipeline (R13 winner) ----------------
__global__ void scan_k(const float* __restrict__ r, const float* __restrict__ k,
                       const float* __restrict__ v,
                       const float* __restrict__ decay, const float* __restrict__ bonus) {
    int h  = blockIdx.x >> 1;
    int vh = blockIdx.x & 1;
    int b  = blockIdx.y;
    int dir = blockIdx.z;
    int tid = threadIdx.x;
    int vcol  = vh * 32 + (tid >> 2);
    int kc    = tid & 3;
    int kbase = kc * 16;

    float Sst[16], wr_[16], ur_[16];
#pragma unroll
    for (int i = 0; i < 16; i++) {
        Sst[i] = 0.f;
        float d = decay[h * HD + kbase + i];
        wr_[i] = expf(-expf(d));
        ur_[i] = bonus[h * HD + kbase + i];
    }
    float* yo = dir ? g_yb : g_yf;

    __shared__ float sbuf[4 * 64 + 4 * 64 + 4 * 32];
    float* s_r = sbuf;
    float* s_k = sbuf + 256;
    float* s_v = sbuf + 512;
    uint32_t sb = smem_u32(sbuf);

    auto sidx = [&](int s) -> size_t {
        int idx = dir ? (SS - 1 - s) : s;
        return ((size_t)(b * SS + idx)) * DM + h * HD;
    };

    auto issue = [&](int s) {
        if (s < SS) {
            size_t base = sidx(s);
            int st = s & 3;
            if (tid < 16)
                cp_async16(sb + (uint32_t)(st * 64 + tid * 4) * 4, r + base + tid * 4);
            else if (tid < 32)
                cp_async16(sb + (uint32_t)(256 + st * 64 + (tid - 16) * 4) * 4, k + base + (tid - 16) * 4);
            else if (tid < 40)
                cp_async16(sb + (uint32_t)(512 + st * 32 + (tid - 32) * 4) * 4, v + base + vh * 32 + (tid - 32) * 4);
        }
        CP_COMMIT();
    };

    issue(0); issue(1); issue(2);

    int vloc = tid >> 2;
    for (int s = 0; s < SS; s++) {
        CP_WAIT2();
        __syncthreads();
        int st = s & 3;
        float vv = s_v[st * 32 + vloc];
        const float* kr = s_k + st * 64 + kbase;
        const float* rp = s_r + st * 64 + kbase;
        float y = 0.f;
#pragma unroll
        for (int i = 0; i < 16; i++) {
            float kk  = kr[i];
            float rv  = rp[i];
            float kv  = kk * vv;
            float tmp = fmaf(ur_[i], kv, Sst[i]);
            y = fmaf(rv, tmp, y);
            Sst[i] = fmaf(wr_[i], Sst[i], kv);
        }
        y += __shfl_xor_sync(0xffffffffu, y, 1);
        y += __shfl_xor_sync(0xffffffffu, y, 2);
        if (kc == 0) yo[sidx(s) + vcol] = y;
        issue(s + 3);
    }
}

// ---------------- router ----------------
__global__ void router_k(const float* __restrict__ xn2, const float* __restrict__ rw) {
    int t = blockIdx.x, tid = threadIdx.x;
    __shared__ float sx[DM];
    __shared__ float slog[8];
    const float* xr = xn2 + (size_t)t * DM;
    for (int i = tid; i < DM; i += 256) sx[i] = xr[i];
    __syncthreads();
    int w = tid >> 5, l = tid & 31;
    float acc = 0.f;
    for (int d = l; d < DM; d += 32) acc = fmaf(sx[d], rw[d * EE + w], acc);
    for (int off = 16; off; off >>= 1) acc += __shfl_xor_sync(0xffffffffu, acc, off);
    if (l == 0) slog[w] = acc;
    __syncthreads();
    if (tid == 0) {
        float mx = -1e30f;
        for (int e = 0; e < EE; e++) mx = fmaxf(mx, slog[e]);
        float p[EE], sum = 0.f;
        for (int e = 0; e < EE; e++) { p[e] = expf(slog[e] - mx); sum += p[e]; }
        float inv = 1.f / sum;
        int e0 = 0; float b0 = -1.f;
        for (int e = 0; e < EE; e++) { p[e] *= inv; if (p[e] > b0) { b0 = p[e]; e0 = e; } }
        int e1 = -1; float b1 = -1.f;
        for (int e = 0; e < EE; e++) { if (e == e0) continue; if (p[e] > b1) { b1 = p[e]; e1 = e; } }
        float gs = 1.f / (b0 + b1);
        g_gate[2 * t]     = b0 * gs;
        g_gate[2 * t + 1] = b1 * gs;
        int pos0 = atomicAdd(&g_cnt[e0], 1); g_list[e0 * TT + pos0] = 2 * t;
        int pos1 = atomicAdd(&g_cnt[e1], 1); g_list[e1 * TT + pos1] = 2 * t + 1;
        for (int e = 0; e < EE; e++) atomicAdd(&g_pmean[e], p[e]);
    }
}

// ---------------- shared GEMM geometry ----------------
#define BNw 256
#define BKw 64
#define LDT 72
#define B_TYPE_B  (256 * LDT * 2)          // 36864 bytes
#define CLD 260

// ---------------- WMMA bf16 split GEMM (3-term), 2-stage cp.async (R10 config) ----------------
// MODE 0 = QKV (z 0..2), 1 = WO (+resid)
template <int BMT> struct GCfg {
    static constexpr int ATB   = BMT * LDT * 2;
    static constexpr int STAGE = 2 * ATB + 2 * B_TYPE_B;
    static constexpr int SMEM  = 2 * STAGE;
};

template <int MODE, int BMT>
__global__ void __launch_bounds__(256, 1)
wgemm_k(const bf16* __restrict__ Ah, const bf16* __restrict__ Al,
        const bf16* __restrict__ Bh, const bf16* __restrict__ Bl,
        const float* __restrict__ resid, float* __restrict__ Cf,
        int M, int N, int K) {
    constexpr int MI   = BMT / 32;
    constexpr int AITS = BMT / 32;
    constexpr int ATB  = GCfg<BMT>::ATB;
    constexpr int STG  = GCfg<BMT>::STAGE;
    constexpr int NPASS = BMT / 64;

    int z = blockIdx.z;
    int bx = blockIdx.x, by = blockIdx.y;

    size_t boff = (MODE == 0) ? (size_t)z * DM * DM : 0;
    const bf16* bhg = Bh + boff;
    const bf16* blg = Bl + boff;
    float* cf = (MODE == 0) ? Cf + (size_t)z * TT * DM : Cf;

    extern __shared__ char smem[];
    uint32_t sb = smem_u32(smem);

    int tid = threadIdx.x;
    int wid = tid >> 5;
    int wm = wid & 1;
    int wn = wid >> 1;

    size_t a_src[AITS]; uint32_t a_so[AITS];
#pragma unroll
    for (int it = 0; it < AITS; it++) {
        int idx = tid + it * 256;
        int row = idx >> 3, seg = idx & 7;
        int ar = by * BMT + row;
        a_src[it] = (size_t)ar * K + seg * 8;
        a_so[it] = (uint32_t)((row * LDT + seg * 8) * 2);
    }
    size_t b_src[8]; uint32_t b_so[8];
#pragma unroll
    for (int it = 0; it < 8; it++) {
        int idx = tid + it * 256;
        int row = idx >> 3, seg = idx & 7;
        b_src[it] = (size_t)(bx * BNw + row) * K + seg * 8;
        b_so[it] = (uint32_t)((row * LDT + seg * 8) * 2);
    }

    const int NC = K / BKw;
    auto issue = [&](int ci, int buf) {
        if (ci < NC) {
            int k0 = ci * BKw;
            uint32_t base = sb + buf * STG;
#pragma unroll
            for (int it = 0; it < AITS; it++) {
                cp_async16(base + a_so[it],       Ah + a_src[it] + k0);
                cp_async16(base + ATB + a_so[it], Al + a_src[it] + k0);
            }
#pragma unroll
            for (int it = 0; it < 8; it++) {
                cp_async16(base + 2 * ATB + b_so[it],            bhg + b_src[it] + k0);
                cp_async16(base + 2 * ATB + B_TYPE_B + b_so[it], blg + b_src[it] + k0);
            }
        }
        CP_COMMIT();
    };

    wmma::fragment<wmma::accumulator, 16, 16, 16, float> c[MI][4];
#pragma unroll
    for (int mi = 0; mi < MI; mi++)
#pragma unroll
        for (int ni = 0; ni < 4; ni++) wmma::fill_fragment(c[mi][ni], 0.f);

    issue(0, 0);
    issue(1, 1);

    for (int i = 0; i < NC; i++) {
        CP_WAIT1();
        __syncthreads();
        int buf = i & 1;
        const bf16* sAh = (const bf16*)(smem + buf * STG);
        const bf16* sAl = (const bf16*)(smem + buf * STG + ATB);
        const bf16* sBh = (const bf16*)(smem + buf * STG + 2 * ATB);
        const bf16* sBl = (const bf16*)(smem + buf * STG + 2 * ATB + B_TYPE_B);
#pragma unroll
        for (int kk = 0; kk < 4; kk++) {
            wmma::fragment<wmma::matrix_a, 16, 16, 16, bf16, wmma::row_major> ah[MI], al[MI];
#pragma unroll
            for (int mi = 0; mi < MI; mi++) {
                wmma::load_matrix_sync(ah[mi], sAh + (wm * (BMT / 2) + mi * 16) * LDT + kk * 16, LDT);
                wmma::load_matrix_sync(al[mi], sAl + (wm * (BMT / 2) + mi * 16) * LDT + kk * 16, LDT);
            }
#pragma unroll
            for (int ni = 0; ni < 4; ni++) {
                wmma::fragment<wmma::matrix_b, 16, 16, 16, bf16, wmma::col_major> bhf, blf;
                wmma::load_matrix_sync(bhf, sBh + (wn * 64 + ni * 16) * LDT + kk * 16, LDT);
                wmma::load_matrix_sync(blf, sBl + (wn * 64 + ni * 16) * LDT + kk * 16, LDT);
#pragma unroll
                for (int mi = 0; mi < MI; mi++) {
                    wmma::mma_sync(c[mi][ni], ah[mi], bhf, c[mi][ni]);
                    wmma::mma_sync(c[mi][ni], ah[mi], blf, c[mi][ni]);
                    wmma::mma_sync(c[mi][ni], al[mi], bhf, c[mi][ni]);
                }
            }
        }
        __syncthreads();
        issue(i + 2, buf);
    }

    float* sC = (float*)smem;
    int lrow = tid >> 2;
    int cseg = (tid & 3) * 64;
#pragma unroll
    for (int pass = 0; pass < NPASS; pass++) {
        __syncthreads();
        if ((wm * (BMT / 2)) / 64 == pass) {
            int rbase = (wm * (BMT / 2)) % 64;
#pragma unroll
            for (int mi = 0; mi < MI; mi++)
#pragma unroll
                for (int ni = 0; ni < 4; ni++)
                    wmma::store_matrix_sync(sC + (rbase + mi * 16) * CLD + wn * 64 + ni * 16,
                                            c[mi][ni], CLD, wmma::mem_row_major);
        }
        __syncthreads();
        int arow = by * BMT + pass * 64 + lrow;
        const float* src = sC + lrow * CLD + cseg;
        size_t ro = (size_t)arow * N + bx * BNw + cseg;
#pragma unroll
        for (int j = 0; j < 16; j++) {
            float4 v = *(const float4*)(src + 4 * j);
            if (MODE == 1) {
                float4 rs = *(const float4*)(resid + ro + 4 * j);
                v.x += rs.x; v.y += rs.y; v.z += rs.z; v.w += rs.w;
            }
            *(float4*)(cf + ro + 4 * j) = v;
        }
    }
}

// ---------------- WMMA fp16 2-term GEMM (MoE): D = A*Bh + A*Bl ----------------
// MODE 2 = up (gather token, silu -> fp16 h), MODE 3 = down (gather pair, *gate -> fp32)
#define H_ATB   (128 * LDT * 2)                 // 18432
#define H_STAGE (H_ATB + 2 * B_TYPE_B)          // 92160
#define H_SMEM  (2 * H_STAGE)                   // 184320

template <int MODE>
__global__ void __launch_bounds__(256, 1)
hgemm_k(const f16* __restrict__ A, const f16* __restrict__ Bh, const f16* __restrict__ Bl,
        float* __restrict__ Cf, f16* __restrict__ Ch, int N, int K) {
    constexpr int MI = 4;

    int z = blockIdx.z;
    int bx = blockIdx.x, by = blockIdx.y;
    int Mrows = g_cnt[z];
    const int* list = g_list + z * TT;
    if (by * 128 >= Mrows) return;

    size_t boff = (MODE == 2) ? (size_t)z * DFFc * DM : (size_t)z * DM * DFFc;
    const f16* bhg = Bh + boff;
    const f16* blg = Bl + boff;

    extern __shared__ char smem[];
    uint32_t sb = smem_u32(smem);

    int tid = threadIdx.x;
    int wid = tid >> 5;
    int wm = wid & 1;
    int wn = wid >> 1;

    size_t a_src[4]; uint32_t a_so[4];
#pragma unroll
    for (int it = 0; it < 4; it++) {
        int idx = tid + it * 256;
        int row = idx >> 3, seg = idx & 7;
        int ar = by * 128 + row;
        int rc = ar < Mrows ? ar : (Mrows - 1);
        int p = list[rc];
        ar = (MODE == 2) ? (p >> 1) : p;
        a_src[it] = (size_t)ar * K + seg * 8;
        a_so[it] = (uint32_t)((row * LDT + seg * 8) * 2);
    }
    size_t b_src[8]; uint32_t b_so[8];
#pragma unroll
    for (int it = 0; it < 8; it++) {
        int idx = tid + it * 256;
        int row = idx >> 3, seg = idx & 7;
        b_src[it] = (size_t)(bx * BNw + row) * K + seg * 8;
        b_so[it] = (uint32_t)((row * LDT + seg * 8) * 2);
    }

    const int NC = K / BKw;
    auto issue = [&](int ci, int buf) {
        if (ci < NC) {
            int k0 = ci * BKw;
            uint32_t base = sb + buf * H_STAGE;
#pragma unroll
            for (int it = 0; it < 4; it++)
                cp_async16(base + a_so[it], A + a_src[it] + k0);
#pragma unroll
            for (int it = 0; it < 8; it++) {
                cp_async16(base + H_ATB + b_so[it],            bhg + b_src[it] + k0);
                cp_async16(base + H_ATB + B_TYPE_B + b_so[it], blg + b_src[it] + k0);
            }
        }
        CP_COMMIT();
    };

    wmma::fragment<wmma::accumulator, 16, 16, 16, float> c[MI][4];
#pragma unroll
    for (int mi = 0; mi < MI; mi++)
#pragma unroll
        for (int ni = 0; ni < 4; ni++) wmma::fill_fragment(c[mi][ni], 0.f);

    issue(0, 0);
    issue(1, 1);

    for (int i = 0; i < NC; i++) {
        CP_WAIT1();
        __syncthreads();
        int buf = i & 1;
        const f16* sA  = (const f16*)(smem + buf * H_STAGE);
        const f16* sBh = (const f16*)(smem + buf * H_STAGE + H_ATB);
        const f16* sBl = (const f16*)(smem + buf * H_STAGE + H_ATB + B_TYPE_B);
#pragma unroll
        for (int kk = 0; kk < 4; kk++) {
            wmma::fragment<wmma::matrix_a, 16, 16, 16, f16, wmma::row_major> a[MI];
#pragma unroll
            for (int mi = 0; mi < MI; mi++)
                wmma::load_matrix_sync(a[mi], sA + (wm * 64 + mi * 16) * LDT + kk * 16, LDT);
#pragma unroll
            for (int ni = 0; ni < 4; ni++) {
                wmma::fragment<wmma::matrix_b, 16, 16, 16, f16, wmma::col_major> bhf, blf;
                wmma::load_matrix_sync(bhf, sBh + (wn * 64 + ni * 16) * LDT + kk * 16, LDT);
                wmma::load_matrix_sync(blf, sBl + (wn * 64 + ni * 16) * LDT + kk * 16, LDT);
#pragma unroll
                for (int mi = 0; mi < MI; mi++) {
                    wmma::mma_sync(c[mi][ni], a[mi], bhf, c[mi][ni]);
                    wmma::mma_sync(c[mi][ni], a[mi], blf, c[mi][ni]);
                }
            }
        }
        __syncthreads();
        issue(i + 2, buf);
    }

    float* sC = (float*)smem;
    int lrow = tid >> 2;
    int cseg = (tid & 3) * 64;
#pragma unroll
    for (int pass = 0; pass < 2; pass++) {
        __syncthreads();
        if (wm == pass) {
#pragma unroll
            for (int mi = 0; mi < MI; mi++)
#pragma unroll
                for (int ni = 0; ni < 4; ni++)
                    wmma::store_matrix_sync(sC + (mi * 16) * CLD + wn * 64 + ni * 16,
                                            c[mi][ni], CLD, wmma::mem_row_major);
        }
        __syncthreads();
        int arow = by * 128 + pass * 64 + lrow;
        if (arow >= Mrows) continue;
        const float* src = sC + lrow * CLD + cseg;
        int colb = bx * BNw + cseg;
        int p = list[arow];
        if (MODE == 2) {
            size_t ro = (size_t)p * DFFc + colb;
#pragma unroll
            for (int j = 0; j < 32; j++) {
                float v0 = src[2 * j], v1 = src[2 * j + 1];
                v0 = v0 / (1.f + expf(-v0));
                v1 = v1 / (1.f + expf(-v1));
                __half2 hv; hv.x = __float2half_rn(v0); hv.y = __float2half_rn(v1);
                *((__half2*)(Ch + ro) + j) = hv;
            }
        } else {
            float gate = g_gate[p];
            size_t ro = (size_t)p * DM + colb;
#pragma unroll
            for (int j = 0; j < 16; j++) {
                float4 v = *(const float4*)(src + 4 * j);
                v.x *= gate; v.y *= gate; v.z *= gate; v.w *= gate;
                *(float4*)(Cf + ro + 4 * j) = v;
            }
        }
    }
}

// ---------------- finalize ----------------
__global__ void finalize_k(float* __restrict__ out, int out_size) {
    int t = blockIdx.x;
    for (int i = threadIdx.x; i < DM; i += 256) {
        size_t o = (size_t)t * DM + i;
        out[o] = g_x1[o] + g_moe[(size_t)(2 * t) * DM + i] + g_moe[(size_t)(2 * t + 1) * DM + i];
    }
    if (blockIdx.x == 0 && threadIdx.x == 0 && out_size > TT * DM) {
        float aux = 0.f;
        for (int e = 0; e < EE; e++)
            aux += ((float)g_cnt[e] / (float)(TT * 2)) * (g_pmean[e] / (float)TT);
        out[out_size - 1] = aux * (float)EE;
    }
}

// ---------------- host launcher ----------------
extern "C" void kernel_launch(void* const* d_in, const int* in_sizes, int n_in,
                              void* d_out, int out_size) {
    const float* x     = (const float*)d_in[0];
    const float* n1w   = (const float*)d_in[2];
    const float* n2w   = (const float*)d_in[3];
    const float* Wr    = (const float*)d_in[4];
    const float* Wk    = (const float*)d_in[5];
    const float* Wv    = (const float*)d_in[6];
    const float* Wo    = (const float*)d_in[7];
    const float* decay = (const float*)d_in[8];
    const float* bonus = (const float*)d_in[9];
    const float* rw    = (const float*)d_in[10];
    const float* w1    = (const float*)d_in[11];
    const float* w2    = (const float*)d_in[12];
    float* out = (float*)d_out;

    float *rkv, *yf, *yb, *x1, *xn2, *moe;
    bf16 *xn1h, *xn1l, *yah, *yal, *wqkvh, *wqkvl, *woh, *wol;
    f16 *xn2f, *hf, *w1fh, *w1fl, *w2fh, *w2fl;
    cudaGetSymbolAddress((void**)&rkv,  g_rkv);
    cudaGetSymbolAddress((void**)&yf,   g_yf);
    cudaGetSymbolAddress((void**)&yb,   g_yb);
    cudaGetSymbolAddress((void**)&x1,   g_x1);
    cudaGetSymbolAddress((void**)&xn2,  g_xn2);
    cudaGetSymbolAddress((void**)&moe,  g_moe);
    cudaGetSymbolAddress((void**)&xn1h, g_xn1h);
    cudaGetSymbolAddress((void**)&xn1l, g_xn1l);
    cudaGetSymbolAddress((void**)&yah,  g_yah);
    cudaGetSymbolAddress((void**)&yal,  g_yal);
    cudaGetSymbolAddress((void**)&xn2f, g_xn2f);
    cudaGetSymbolAddress((void**)&hf,   g_hf);
    cudaGetSymbolAddress((void**)&wqkvh, g_wqkvh);
    cudaGetSymbolAddress((void**)&wqkvl, g_wqkvl);
    cudaGetSymbolAddress((void**)&woh,  g_woh);
    cudaGetSymbolAddress((void**)&wol,  g_wol);
    cudaGetSymbolAddress((void**)&w1fh, g_w1fh);
    cudaGetSymbolAddress((void**)&w1fl, g_w1fl);
    cudaGetSymbolAddress((void**)&w2fh, g_w2fh);
    cudaGetSymbolAddress((void**)&w2fl, g_w2fl);

    cudaFuncSetAttribute(wgemm_k<0, 128>, cudaFuncAttributeMaxDynamicSharedMemorySize, GCfg<128>::SMEM);
    cudaFuncSetAttribute(wgemm_k<1, 64>,  cudaFuncAttributeMaxDynamicSharedMemorySize, GCfg<64>::SMEM);
    cudaFuncSetAttribute(hgemm_k<2>, cudaFuncAttributeMaxDynamicSharedMemorySize, H_SMEM);
    cudaFuncSetAttribute(hgemm_k<3>, cudaFuncAttributeMaxDynamicSharedMemorySize, H_SMEM);

    zero_k<<<1, 32>>>();

    dim3 tb(32, 8);
    tsplit_k<<<dim3(DM / 32, DM / 32, 1), tb>>>(Wr, wqkvh,               wqkvl,               DM, DM);
    tsplit_k<<<dim3(DM / 32, DM / 32, 1), tb>>>(Wk, wqkvh + DM * DM,     wqkvl + DM * DM,     DM, DM);
    tsplit_k<<<dim3(DM / 32, DM / 32, 1), tb>>>(Wv, wqkvh + 2 * DM * DM, wqkvl + 2 * DM * DM, DM, DM);

    rmsnorm_k<<<TT, 256>>>(x, n1w, xn1h, xn1l);

    // QKV (bf16 3-term)
    wgemm_k<0, 128><<<dim3(DM / BNw, TT / 128, 3), 256, GCfg<128>::SMEM>>>(
        xn1h, xn1l, wqkvh, wqkvl, nullptr, rkv, TT, DM, DM);

    scan_k<<<dim3(HH * 2, BB, 2), 128>>>(rkv, rkv + TT * DM, rkv + 2 * TT * DM, decay, bonus);

    tsplit_k<<<dim3(DM / 32, DM / 32, 1), tb>>>(Wo, woh, wol, DM, DM);

    splitadd_k<<<(TT * DM + 255) / 256, 256>>>(yf, yb, yah, yal, TT * DM);

    // x1 = x + (yf+yb) @ Wo (bf16 3-term)
    wgemm_k<1, 64><<<dim3(DM / BNw, TT / 64, 1), 256, GCfg<64>::SMEM>>>(
        yah, yal, woh, wol, x, x1, TT, DM, DM);

    rmsnorm2_k<<<TT, 256>>>(x1, n2w, xn2, xn2f);
    router_k<<<TT, 256>>>(xn2, rw);

    tsplit16_k<<<dim3(DFFc / 32, DM / 32, EE), tb>>>(w1, w1fh, w1fl, DM, DFFc);

    // MoE up (fp16 2-term): h[p] = silu(xn2f[token] @ w1[e]) -> fp16
    hgemm_k<2><<<dim3(DFFc / BNw, TT / 128, EE), 256, H_SMEM>>>(
        xn2f, w1fh, w1fl, nullptr, hf, DFFc, DM);

    tsplit16_k<<<dim3(DM / 32, DFFc / 32, EE), tb>>>(w2, w2fh, w2fl, DFFc, DM);

    // MoE down (fp16 2-term): moe[p] = gate[p] * (hf[p] @ w2[e])
    hgemm_k<3><<<dim3(DM / BNw, TT / 128, EE), 256, H_SMEM>>>(
        hf, w2fh, w2fl, moe, nullptr, DM, DFFc);

    finalize_k<<<TT, 256>>>(out, out_size);
}

// round 15
// speedup vs baseline: 1.6278x; 1.0690x over previous
#include <cuda_runtime.h>
#include <cuda_fp16.h>
#include <mma.h>
#include <math.h>
#include <stdint.h>

using namespace nvcuda;

// Problem constants
#define TT   4096
#define DM   1024
#define HH   16
#define HD   64
#define DFFc 2048
#define EE   8
#define SS   2048
#define BB   2

typedef __half f16;

// ---------------- scratch ----------------
__device__ float g_rkv[3 * TT * DM];
__device__ float g_yf[TT * DM];
__device__ float g_yb[TT * DM];
__device__ float g_x1[TT * DM];
__device__ float g_xn2[TT * DM];
__device__ float g_moe[2 * TT * DM];
__device__ f16   g_xn1f[TT * DM];
__device__ f16   g_yaf[TT * DM];
__device__ f16   g_xn2f[TT * DM];
__device__ f16   g_hf[2 * TT * DFFc];            // 32 MB
__device__ f16   g_wqkvfh[3 * DM * DM], g_wqkvfl[3 * DM * DM];
__device__ f16   g_wofh[DM * DM], g_wofl[DM * DM];
__device__ f16   g_w1fh[EE * DFFc * DM], g_w1fl[EE * DFFc * DM];
__device__ f16   g_w2fh[EE * DM * DFFc], g_w2fl[EE * DM * DFFc];
__device__ float g_gate[2 * TT];
__device__ int   g_list[EE * TT];
__device__ int   g_cnt[EE];
__device__ float g_pmean[EE];

__device__ __forceinline__ uint32_t smem_u32(const void* p) {
    uint32_t a;
    asm("{ .reg .u64 t; cvta.to.shared.u64 t, %1; cvt.u32.u64 %0, t; }" : "=r"(a) : "l"(p));
    return a;
}
__device__ __forceinline__ void cp_async16(uint32_t s, const void* g) {
    asm volatile("cp.async.cg.shared.global [%0], [%1], 16;" :: "r"(s), "l"(g) : "memory");
}
#define CP_COMMIT() asm volatile("cp.async.commit_group;" ::: "memory")
#define CP_WAIT1()  asm volatile("cp.async.wait_group 1;"  ::: "memory")
#define CP_WAIT2()  asm volatile("cp.async.wait_group 2;"  ::: "memory")

// ---------------- small kernels ----------------
__global__ void zero_k() {
    int i = threadIdx.x;
    if (i < EE) { g_cnt[i] = 0; g_pmean[i] = 0.f; }
}

// transpose + split fp16: src [K,N] fp32 (batch z) -> dh/dl [N,K] fp16
__global__ void tsplit16_k(const float* __restrict__ src, f16* __restrict__ dh,
                           f16* __restrict__ dl, int K, int N) {
    int e = blockIdx.z;
    src += (size_t)e * K * N;
    dh  += (size_t)e * N * K;
    dl  += (size_t)e * N * K;
    __shared__ float tile[32][33];
    int n0 = blockIdx.x * 32, k0 = blockIdx.y * 32;
    int tx = threadIdx.x, ty = threadIdx.y;
#pragma unroll
    for (int i = 0; i < 4; i++)
        tile[ty + i * 8][tx] = src[(size_t)(k0 + ty + i * 8) * N + n0 + tx];
    __syncthreads();
    int t = ty * 32 + tx;
#pragma unroll
    for (int it = 0; it < 2; it++) {
        int i = t + it * 256;
        int row = i >> 4;
        int kp  = i & 15;
        float v0 = tile[kp * 2][row];
        float v1 = tile[kp * 2 + 1][row];
        f16 h0 = __float2half_rn(v0);
        f16 h1 = __float2half_rn(v1);
        __half2 hv; hv.x = h0; hv.y = h1;
        __half2 lv;
        lv.x = __float2half_rn(v0 - __half2float(h0));
        lv.y = __float2half_rn(v1 - __half2float(h1));
        size_t o = ((size_t)(n0 + row) * K + k0 + kp * 2) >> 1;
        ((__half2*)dh)[o] = hv;
        ((__half2*)dl)[o] = lv;
    }
}

// ya = fp16(yf + yb)
__global__ void addcvt_k(const float* __restrict__ a, const float* __restrict__ b,
                         f16* __restrict__ o, int n) {
    int i = blockIdx.x * blockDim.x + threadIdx.x;
    if (i >= n) return;
    o[i] = __float2half_rn(a[i] + b[i]);
}

// rmsnorm -> fp16 (+ optional fp32 for router)
template <bool WRITE_F32>
__global__ void rmsnorm_k(const float* __restrict__ x, const float* __restrict__ w,
                          float* __restrict__ ofp, f16* __restrict__ o16) {
    int t = blockIdx.x;
    const float* xr = x + (size_t)t * DM;
    float s = 0.f;
    for (int i = threadIdx.x; i < DM; i += 256) { float v = xr[i]; s += v * v; }
    for (int off = 16; off; off >>= 1) s += __shfl_xor_sync(0xffffffffu, s, off);
    __shared__ float red[8];
    int wrp = threadIdx.x >> 5, ln = threadIdx.x & 31;
    if (ln == 0) red[wrp] = s;
    __syncthreads();
    if (wrp == 0) {
        float v = (ln < 8) ? red[ln] : 0.f;
        for (int off = 4; off; off >>= 1) v += __shfl_xor_sync(0xffffffffu, v, off);
        if (ln == 0) red[0] = v;
    }
    __syncthreads();
    float scale = rsqrtf(red[0] / (float)DM + 1e-6f);
    size_t base = (size_t)t * DM;
    for (int i = threadIdx.x; i < DM; i += 256) {
        float v = xr[i] * scale * w[i];
        if (WRITE_F32) ofp[base + i] = v;
        o16[base + i] = __float2half_rn(v);
    }
}

// ---------------- RWKV bidirectional scan, 4-stage cp.async pipeline ----------------
__global__ void scan_k(const float* __restrict__ r, const float* __restrict__ k,
                       const float* __restrict__ v,
                       const float* __restrict__ decay, const float* __restrict__ bonus) {
    int h  = blockIdx.x >> 1;
    int vh = blockIdx.x & 1;
    int b  = blockIdx.y;
    int dir = blockIdx.z;
    int tid = threadIdx.x;
    int vcol  = vh * 32 + (tid >> 2);
    int kc    = tid & 3;
    int kbase = kc * 16;

    float Sst[16], wr_[16], ur_[16];
#pragma unroll
    for (int i = 0; i < 16; i++) {
        Sst[i] = 0.f;
        float d = decay[h * HD + kbase + i];
        wr_[i] = expf(-expf(d));
        ur_[i] = bonus[h * HD + kbase + i];
    }
    float* yo = dir ? g_yb : g_yf;

    __shared__ float sbuf[4 * 64 + 4 * 64 + 4 * 32];
    float* s_r = sbuf;
    float* s_k = sbuf + 256;
    float* s_v = sbuf + 512;
    uint32_t sb = smem_u32(sbuf);

    auto sidx = [&](int s) -> size_t {
        int idx = dir ? (SS - 1 - s) : s;
        return ((size_t)(b * SS + idx)) * DM + h * HD;
    };

    auto issue = [&](int s) {
        if (s < SS) {
            size_t base = sidx(s);
            int st = s & 3;
            if (tid < 16)
                cp_async16(sb + (uint32_t)(st * 64 + tid * 4) * 4, r + base + tid * 4);
            else if (tid < 32)
                cp_async16(sb + (uint32_t)(256 + st * 64 + (tid - 16) * 4) * 4, k + base + (tid - 16) * 4);
            else if (tid < 40)
                cp_async16(sb + (uint32_t)(512 + st * 32 + (tid - 32) * 4) * 4, v + base + vh * 32 + (tid - 32) * 4);
        }
        CP_COMMIT();
    };

    issue(0); issue(1); issue(2);

    int vloc = tid >> 2;
    for (int s = 0; s < SS; s++) {
        CP_WAIT2();
        __syncthreads();
        int st = s & 3;
        float vv = s_v[st * 32 + vloc];
        const float* kr = s_k + st * 64 + kbase;
        const float* rp = s_r + st * 64 + kbase;
        float y = 0.f;
#pragma unroll
        for (int i = 0; i < 16; i++) {
            float kk  = kr[i];
            float rv  = rp[i];
            float kv  = kk * vv;
            float tmp = fmaf(ur_[i], kv, Sst[i]);
            y = fmaf(rv, tmp, y);
            Sst[i] = fmaf(wr_[i], Sst[i], kv);
        }
        y += __shfl_xor_sync(0xffffffffu, y, 1);
        y += __shfl_xor_sync(0xffffffffu, y, 2);
        if (kc == 0) yo[sidx(s) + vcol] = y;
        issue(s + 3);
    }
}

// ---------------- router ----------------
__global__ void router_k(const float* __restrict__ xn2, const float* __restrict__ rw) {
    int t = blockIdx.x, tid = threadIdx.x;
    __shared__ float sx[DM];
    __shared__ float slog[8];
    const float* xr = xn2 + (size_t)t * DM;
    for (int i = tid; i < DM; i += 256) sx[i] = xr[i];
    __syncthreads();
    int w = tid >> 5, l = tid & 31;
    float acc = 0.f;
    for (int d = l; d < DM; d += 32) acc = fmaf(sx[d], rw[d * EE + w], acc);
    for (int off = 16; off; off >>= 1) acc += __shfl_xor_sync(0xffffffffu, acc, off);
    if (l == 0) slog[w] = acc;
    __syncthreads();
    if (tid == 0) {
        float mx = -1e30f;
        for (int e = 0; e < EE; e++) mx = fmaxf(mx, slog[e]);
        float p[EE], sum = 0.f;
        for (int e = 0; e < EE; e++) { p[e] = expf(slog[e] - mx); sum += p[e]; }
        float inv = 1.f / sum;
        int e0 = 0; float b0 = -1.f;
        for (int e = 0; e < EE; e++) { p[e] *= inv; if (p[e] > b0) { b0 = p[e]; e0 = e; } }
        int e1 = -1; float b1 = -1.f;
        for (int e = 0; e < EE; e++) { if (e == e0) continue; if (p[e] > b1) { b1 = p[e]; e1 = e; } }
        float gs = 1.f / (b0 + b1);
        g_gate[2 * t]     = b0 * gs;
        g_gate[2 * t + 1] = b1 * gs;
        int pos0 = atomicAdd(&g_cnt[e0], 1); g_list[e0 * TT + pos0] = 2 * t;
        int pos1 = atomicAdd(&g_cnt[e1], 1); g_list[e1 * TT + pos1] = 2 * t + 1;
        for (int e = 0; e < EE; e++) atomicAdd(&g_pmean[e], p[e]);
    }
}

// ---------------- unified fp16 2-term GEMM: D = A*Bh + A*Bl ----------------
// CTA tile BMT x 256, BK=64, 8 warps (2M x 4N), warp tile (BMT/2) x 64.
// MODE 0 = QKV (z 0..2 selects weight slab, C = rkv + z*TT*DM)
// MODE 1 = WO (+resid)
// MODE 2 = MoE up (gather token, silu -> fp16 h)
// MODE 3 = MoE down (gather pair, *gate -> fp32)
#define BNw 256
#define BKw 64
#define LDT 72
#define B_TYPE_B  (256 * LDT * 2)          // 36864 bytes
#define CLD 260

template <int BMT> struct HCfg {
    static constexpr int ATB   = BMT * LDT * 2;
    static constexpr int STAGE = ATB + 2 * B_TYPE_B;
    static constexpr int SMEM  = 2 * STAGE;
};

template <int MODE, int BMT>
__global__ void __launch_bounds__(256, 1)
hgemm_k(const f16* __restrict__ A, const f16* __restrict__ Bh, const f16* __restrict__ Bl,
        const float* __restrict__ resid, float* __restrict__ Cf, f16* __restrict__ Ch,
        int M, int N, int K) {
    constexpr int MI   = BMT / 32;
    constexpr int AITS = BMT / 32;   // BMT rows * 8 segs / 256 threads
    constexpr int ATB  = HCfg<BMT>::ATB;
    constexpr int STG  = HCfg<BMT>::STAGE;
    constexpr int NPASS = BMT / 64;

    int z = blockIdx.z;
    int bx = blockIdx.x, by = blockIdx.y;
    int Mrows = M;
    const int* list = nullptr;
    if (MODE == 2 || MODE == 3) { Mrows = g_cnt[z]; list = g_list + z * TT; }
    if (by * BMT >= Mrows) return;

    size_t boff = 0;
    if (MODE == 0) boff = (size_t)z * DM * DM;
    if (MODE == 2) boff = (size_t)z * DFFc * DM;
    if (MODE == 3) boff = (size_t)z * DM * DFFc;
    const f16* bhg = Bh + boff;
    const f16* blg = Bl + boff;
    float* cf = Cf;
    if (MODE == 0) cf = Cf + (size_t)z * TT * DM;

    extern __shared__ char smem[];
    uint32_t sb = smem_u32(smem);

    int tid = threadIdx.x;
    int wid = tid >> 5;
    int wm = wid & 1;
    int wn = wid >> 1;

    size_t a_src[AITS]; uint32_t a_so[AITS];
#pragma unroll
    for (int it = 0; it < AITS; it++) {
        int idx = tid + it * 256;
        int row = idx >> 3, seg = idx & 7;
        int ar = by * BMT + row;
        if (MODE == 2 || MODE == 3) {
            int rc = ar < Mrows ? ar : (Mrows - 1);
            int p = list[rc];
            ar = (MODE == 2) ? (p >> 1) : p;
        }
        a_src[it] = (size_t)ar * K + seg * 8;
        a_so[it] = (uint32_t)((row * LDT + seg * 8) * 2);
    }
    size_t b_src[8]; uint32_t b_so[8];
#pragma unroll
    for (int it = 0; it < 8; it++) {
        int idx = tid + it * 256;
        int row = idx >> 3, seg = idx & 7;
        b_src[it] = (size_t)(bx * BNw + row) * K + seg * 8;
        b_so[it] = (uint32_t)((row * LDT + seg * 8) * 2);
    }

    const int NC = K / BKw;
    auto issue = [&](int ci, int buf) {
        if (ci < NC) {
            int k0 = ci * BKw;
            uint32_t base = sb + buf * STG;
#pragma unroll
            for (int it = 0; it < AITS; it++)
                cp_async16(base + a_so[it], A + a_src[it] + k0);
#pragma unroll
            for (int it = 0; it < 8; it++) {
                cp_async16(base + ATB + b_so[it],            bhg + b_src[it] + k0);
                cp_async16(base + ATB + B_TYPE_B + b_so[it], blg + b_src[it] + k0);
            }
        }
        CP_COMMIT();
    };

    wmma::fragment<wmma::accumulator, 16, 16, 16, float> c[MI][4];
#pragma unroll
    for (int mi = 0; mi < MI; mi++)
#pragma unroll
        for (int ni = 0; ni < 4; ni++) wmma::fill_fragment(c[mi][ni], 0.f);

    issue(0, 0);
    issue(1, 1);

    for (int i = 0; i < NC; i++) {
        CP_WAIT1();
        __syncthreads();
        int buf = i & 1;
        const f16* sA  = (const f16*)(smem + buf * STG);
        const f16* sBh = (const f16*)(smem + buf * STG + ATB);
        const f16* sBl = (const f16*)(smem + buf * STG + ATB + B_TYPE_B);
#pragma unroll
        for (int kk = 0; kk < 4; kk++) {
            wmma::fragment<wmma::matrix_a, 16, 16, 16, f16, wmma::row_major> a[MI];
#pragma unroll
            for (int mi = 0; mi < MI; mi++)
                wmma::load_matrix_sync(a[mi], sA + (wm * (BMT / 2) + mi * 16) * LDT + kk * 16, LDT);
#pragma unroll
            for (int ni = 0; ni < 4; ni++) {
                wmma::fragment<wmma::matrix_b, 16, 16, 16, f16, wmma::col_major> bhf, blf;
                wmma::load_matrix_sync(bhf, sBh + (wn * 64 + ni * 16) * LDT + kk * 16, LDT);
                wmma::load_matrix_sync(blf, sBl + (wn * 64 + ni * 16) * LDT + kk * 16, LDT);
#pragma unroll
                for (int mi = 0; mi < MI; mi++) {
                    wmma::mma_sync(c[mi][ni], a[mi], bhf, c[mi][ni]);
                    wmma::mma_sync(c[mi][ni], a[mi], blf, c[mi][ni]);
                }
            }
        }
        __syncthreads();
        issue(i + 2, buf);
    }

    float* sC = (float*)smem;
    int lrow = tid >> 2;
    int cseg = (tid & 3) * 64;
#pragma unroll
    for (int pass = 0; pass < NPASS; pass++) {
        __syncthreads();
        if ((wm * (BMT / 2)) / 64 == pass) {
            int rbase = (wm * (BMT / 2)) % 64;
#pragma unroll
            for (int mi = 0; mi < MI; mi++)
#pragma unroll
                for (int ni = 0; ni < 4; ni++)
                    wmma::store_matrix_sync(sC + (rbase + mi * 16) * CLD + wn * 64 + ni * 16,
                                            c[mi][ni], CLD, wmma::mem_row_major);
        }
        __syncthreads();
        int arow = by * BMT + pass * 64 + lrow;
        if (arow >= Mrows) continue;
        const float* src = sC + lrow * CLD + cseg;
        int colb = bx * BNw + cseg;
        if (MODE == 2) {
            int p = list[arow];
            size_t ro = (size_t)p * DFFc + colb;
#pragma unroll
            for (int j = 0; j < 32; j++) {
                float v0 = src[2 * j], v1 = src[2 * j + 1];
                v0 = v0 / (1.f + expf(-v0));
                v1 = v1 / (1.f + expf(-v1));
                __half2 hv; hv.x = __float2half_rn(v0); hv.y = __float2half_rn(v1);
                *((__half2*)(Ch + ro) + j) = hv;
            }
        } else if (MODE == 3) {
            int p = list[arow];
            float gate = g_gate[p];
            size_t ro = (size_t)p * DM + colb;
#pragma unroll
            for (int j = 0; j < 16; j++) {
                float4 v = *(const float4*)(src + 4 * j);
                v.x *= gate; v.y *= gate; v.z *= gate; v.w *= gate;
                *(float4*)(Cf + ro + 4 * j) = v;
            }
        } else {
            size_t ro = (size_t)arow * N + colb;
#pragma unroll
            for (int j = 0; j < 16; j++) {
                float4 v = *(const float4*)(src + 4 * j);
                if (MODE == 1) {
                    float4 rs = *(const float4*)(resid + ro + 4 * j);
                    v.x += rs.x; v.y += rs.y; v.z += rs.z; v.w += rs.w;
                }
                *(float4*)(cf + ro + 4 * j) = v;
            }
        }
    }
}

// ---------------- finalize ----------------
__global__ void finalize_k(float* __restrict__ out, int out_size) {
    int t = blockIdx.x;
    for (int i = threadIdx.x; i < DM; i += 256) {
        size_t o = (size_t)t * DM + i;
        out[o] = g_x1[o] + g_moe[(size_t)(2 * t) * DM + i] + g_moe[(size_t)(2 * t + 1) * DM + i];
    }
    if (blockIdx.x == 0 && threadIdx.x == 0 && out_size > TT * DM) {
        float aux = 0.f;
        for (int e = 0; e < EE; e++)
            aux += ((float)g_cnt[e] / (float)(TT * 2)) * (g_pmean[e] / (float)TT);
        out[out_size - 1] = aux * (float)EE;
    }
}

// ---------------- host launcher ----------------
extern "C" void kernel_launch(void* const* d_in, const int* in_sizes, int n_in,
                              void* d_out, int out_size) {
    const float* x     = (const float*)d_in[0];
    const float* n1w   = (const float*)d_in[2];
    const float* n2w   = (const float*)d_in[3];
    const float* Wr    = (const float*)d_in[4];
    const float* Wk    = (const float*)d_in[5];
    const float* Wv    = (const float*)d_in[6];
    const float* Wo    = (const float*)d_in[7];
    const float* decay = (const float*)d_in[8];
    const float* bonus = (const float*)d_in[9];
    const float* rw    = (const float*)d_in[10];
    const float* w1    = (const float*)d_in[11];
    const float* w2    = (const float*)d_in[12];
    float* out = (float*)d_out;

    float *rkv, *yf, *yb, *x1, *xn2, *moe;
    f16 *xn1f, *yaf, *xn2f, *hf;
    f16 *wqkvfh, *wqkvfl, *wofh, *wofl, *w1fh, *w1fl, *w2fh, *w2fl;
    cudaGetSymbolAddress((void**)&rkv,  g_rkv);
    cudaGetSymbolAddress((void**)&yf,   g_yf);
    cudaGetSymbolAddress((void**)&yb,   g_yb);
    cudaGetSymbolAddress((void**)&x1,   g_x1);
    cudaGetSymbolAddress((void**)&xn2,  g_xn2);
    cudaGetSymbolAddress((void**)&moe,  g_moe);
    cudaGetSymbolAddress((void**)&xn1f, g_xn1f);
    cudaGetSymbolAddress((void**)&yaf,  g_yaf);
    cudaGetSymbolAddress((void**)&xn2f, g_xn2f);
    cudaGetSymbolAddress((void**)&hf,   g_hf);
    cudaGetSymbolAddress((void**)&wqkvfh, g_wqkvfh);
    cudaGetSymbolAddress((void**)&wqkvfl, g_wqkvfl);
    cudaGetSymbolAddress((void**)&wofh, g_wofh);
    cudaGetSymbolAddress((void**)&wofl, g_wofl);
    cudaGetSymbolAddress((void**)&w1fh, g_w1fh);
    cudaGetSymbolAddress((void**)&w1fl, g_w1fl);
    cudaGetSymbolAddress((void**)&w2fh, g_w2fh);
    cudaGetSymbolAddress((void**)&w2fl, g_w2fl);

    cudaFuncSetAttribute(hgemm_k<0, 128>, cudaFuncAttributeMaxDynamicSharedMemorySize, HCfg<128>::SMEM);
    cudaFuncSetAttribute(hgemm_k<1, 64>,  cudaFuncAttributeMaxDynamicSharedMemorySize, HCfg<64>::SMEM);
    cudaFuncSetAttribute(hgemm_k<2, 128>, cudaFuncAttributeMaxDynamicSharedMemorySize, HCfg<128>::SMEM);
    cudaFuncSetAttribute(hgemm_k<3, 128>, cudaFuncAttributeMaxDynamicSharedMemorySize, HCfg<128>::SMEM);

    zero_k<<<1, 32>>>();

    dim3 tb(32, 8);
    tsplit16_k<<<dim3(DM / 32, DM / 32, 1), tb>>>(Wr, wqkvfh,               wqkvfl,               DM, DM);
    tsplit16_k<<<dim3(DM / 32, DM / 32, 1), tb>>>(Wk, wqkvfh + DM * DM,     wqkvfl + DM * DM,     DM, DM);
    tsplit16_k<<<dim3(DM / 32, DM / 32, 1), tb>>>(Wv, wqkvfh + 2 * DM * DM, wqkvfl + 2 * DM * DM, DM, DM);

    rmsnorm_k<false><<<TT, 256>>>(x, n1w, nullptr, xn1f);

    // QKV (fp16 2-term)
    hgemm_k<0, 128><<<dim3(DM / BNw, TT / 128, 3), 256, HCfg<128>::SMEM>>>(
        xn1f, wqkvfh, wqkvfl, nullptr, rkv, nullptr, TT, DM, DM);

    scan_k<<<dim3(HH * 2, BB, 2), 128>>>(rkv, rkv + TT * DM, rkv + 2 * TT * DM, decay, bonus);

    tsplit16_k<<<dim3(DM / 32, DM / 32, 1), tb>>>(Wo, wofh, wofl, DM, DM);

    addcvt_k<<<(TT * DM + 255) / 256, 256>>>(yf, yb, yaf, TT * DM);

    // x1 = x + (yf+yb) @ Wo (fp16 2-term, BMT=64 for occupancy)
    hgemm_k<1, 64><<<dim3(DM / BNw, TT / 64, 1), 256, HCfg<64>::SMEM>>>(
        yaf, wofh, wofl, x, x1, nullptr, TT, DM, DM);

    rmsnorm_k<true><<<TT, 256>>>(x1, n2w, xn2, xn2f);
    router_k<<<TT, 256>>>(xn2, rw);

    tsplit16_k<<<dim3(DFFc / 32, DM / 32, EE), tb>>>(w1, w1fh, w1fl, DM, DFFc);

    // MoE up (fp16 2-term): h[p] = silu(xn2f[token] @ w1[e]) -> fp16
    hgemm_k<2, 128><<<dim3(DFFc / BNw, TT / 128, EE), 256, HCfg<128>::SMEM>>>(
        xn2f, w1fh, w1fl, nullptr, nullptr, hf, 0, DFFc, DM);

    tsplit16_k<<<dim3(DM / 32, DFFc / 32, EE), tb>>>(w2, w2fh, w2fl, DFFc, DM);

    // MoE down (fp16 2-term): moe[p] = gate[p] * (hf[p] @ w2[e])
    hgemm_k<3, 128><<<dim3(DM / BNw, TT / 128, EE), 256, HCfg<128>::SMEM>>>(
        hf, w2fh, w2fl, nullptr, moe, nullptr, 0, DM, DFFc);

    finalize_k<<<TT, 256>>>(out, out_size);
}

// round 16
// speedup vs baseline: 1.8421x; 1.1316x over previous
#include <cuda_runtime.h>
#include <cuda_fp16.h>
#include <mma.h>
#include <math.h>
#include <stdint.h>

using namespace nvcuda;

// Problem constants
#define TT   4096
#define DM   1024
#define HH   16
#define HD   64
#define DFFc 2048
#define EE   8
#define SS   2048
#define BB   2

typedef __half f16;

// ---------------- scratch ----------------
__device__ float g_rkv[3 * TT * DM];
__device__ float g_yf[TT * DM];
__device__ float g_yb[TT * DM];
__device__ float g_x1[TT * DM];
__device__ float g_xn2[TT * DM];
__device__ float g_moe[2 * TT * DM];
__device__ f16   g_xn1f[TT * DM];
__device__ f16   g_yaf[TT * DM];
__device__ f16   g_xn2f[TT * DM];
__device__ f16   g_hf[2 * TT * DFFc];            // 32 MB
__device__ f16   g_wqkvfh[3 * DM * DM], g_wqkvfl[3 * DM * DM];
__device__ f16   g_wofh[DM * DM], g_wofl[DM * DM];
__device__ f16   g_w1f[EE * DFFc * DM];          // single fp16 (1-term MoE)
__device__ f16   g_w2f[EE * DM * DFFc];
__device__ float g_gate[2 * TT];
__device__ int   g_list[EE * TT];
__device__ int   g_cnt[EE];
__device__ float g_pmean[EE];

__device__ __forceinline__ uint32_t smem_u32(const void* p) {
    uint32_t a;
    asm("{ .reg .u64 t; cvta.to.shared.u64 t, %1; cvt.u32.u64 %0, t; }" : "=r"(a) : "l"(p));
    return a;
}
__device__ __forceinline__ void cp_async16(uint32_t s, const void* g) {
    asm volatile("cp.async.cg.shared.global [%0], [%1], 16;" :: "r"(s), "l"(g) : "memory");
}
#define CP_COMMIT() asm volatile("cp.async.commit_group;" ::: "memory")
#define CP_WAIT1()  asm volatile("cp.async.wait_group 1;"  ::: "memory")
#define CP_WAIT2()  asm volatile("cp.async.wait_group 2;"  ::: "memory")

// ---------------- small kernels ----------------
__global__ void zero_k() {
    int i = threadIdx.x;
    if (i < EE) { g_cnt[i] = 0; g_pmean[i] = 0.f; }
}

// transpose + convert fp16: src [K,N] fp32 (batch z) -> dh (and dl if LO) [N,K] fp16
template <bool LO>
__global__ void tsplit16_k(const float* __restrict__ src, f16* __restrict__ dh,
                           f16* __restrict__ dl, int K, int N) {
    int e = blockIdx.z;
    src += (size_t)e * K * N;
    dh  += (size_t)e * N * K;
    if (LO) dl += (size_t)e * N * K;
    __shared__ float tile[32][33];
    int n0 = blockIdx.x * 32, k0 = blockIdx.y * 32;
    int tx = threadIdx.x, ty = threadIdx.y;
#pragma unroll
    for (int i = 0; i < 4; i++)
        tile[ty + i * 8][tx] = src[(size_t)(k0 + ty + i * 8) * N + n0 + tx];
    __syncthreads();
    int t = ty * 32 + tx;
#pragma unroll
    for (int it = 0; it < 2; it++) {
        int i = t + it * 256;
        int row = i >> 4;
        int kp  = i & 15;
        float v0 = tile[kp * 2][row];
        float v1 = tile[kp * 2 + 1][row];
        f16 h0 = __float2half_rn(v0);
        f16 h1 = __float2half_rn(v1);
        __half2 hv; hv.x = h0; hv.y = h1;
        size_t o = ((size_t)(n0 + row) * K + k0 + kp * 2) >> 1;
        ((__half2*)dh)[o] = hv;
        if (LO) {
            __half2 lv;
            lv.x = __float2half_rn(v0 - __half2float(h0));
            lv.y = __float2half_rn(v1 - __half2float(h1));
            ((__half2*)dl)[o] = lv;
        }
    }
}

// ya = fp16(yf + yb)
__global__ void addcvt_k(const float* __restrict__ a, const float* __restrict__ b,
                         f16* __restrict__ o, int n) {
    int i = blockIdx.x * blockDim.x + threadIdx.x;
    if (i >= n) return;
    o[i] = __float2half_rn(a[i] + b[i]);
}

// rmsnorm -> fp16 (+ optional fp32 for router)
template <bool WRITE_F32>
__global__ void rmsnorm_k(const float* __restrict__ x, const float* __restrict__ w,
                          float* __restrict__ ofp, f16* __restrict__ o16) {
    int t = blockIdx.x;
    const float* xr = x + (size_t)t * DM;
    float s = 0.f;
    for (int i = threadIdx.x; i < DM; i += 256) { float v = xr[i]; s += v * v; }
    for (int off = 16; off; off >>= 1) s += __shfl_xor_sync(0xffffffffu, s, off);
    __shared__ float red[8];
    int wrp = threadIdx.x >> 5, ln = threadIdx.x & 31;
    if (ln == 0) red[wrp] = s;
    __syncthreads();
    if (wrp == 0) {
        float v = (ln < 8) ? red[ln] : 0.f;
        for (int off = 4; off; off >>= 1) v += __shfl_xor_sync(0xffffffffu, v, off);
        if (ln == 0) red[0] = v;
    }
    __syncthreads();
    float scale = rsqrtf(red[0] / (float)DM + 1e-6f);
    size_t base = (size_t)t * DM;
    for (int i = threadIdx.x; i < DM; i += 256) {
        float v = xr[i] * scale * w[i];
        if (WRITE_F32) ofp[base + i] = v;
        o16[base + i] = __float2half_rn(v);
    }
}

// ---------------- RWKV bidirectional scan, 4-stage cp.async pipeline ----------------
__global__ void scan_k(const float* __restrict__ r, const float* __restrict__ k,
                       const float* __restrict__ v,
                       const float* __restrict__ decay, const float* __restrict__ bonus) {
    int h  = blockIdx.x >> 1;
    int vh = blockIdx.x & 1;
    int b  = blockIdx.y;
    int dir = blockIdx.z;
    int tid = threadIdx.x;
    int vcol  = vh * 32 + (tid >> 2);
    int kc    = tid & 3;
    int kbase = kc * 16;

    float Sst[16], wr_[16], ur_[16];
#pragma unroll
    for (int i = 0; i < 16; i++) {
        Sst[i] = 0.f;
        float d = decay[h * HD + kbase + i];
        wr_[i] = expf(-expf(d));
        ur_[i] = bonus[h * HD + kbase + i];
    }
    float* yo = dir ? g_yb : g_yf;

    __shared__ float sbuf[4 * 64 + 4 * 64 + 4 * 32];
    float* s_r = sbuf;
    float* s_k = sbuf + 256;
    float* s_v = sbuf + 512;
    uint32_t sb = smem_u32(sbuf);

    auto sidx = [&](int s) -> size_t {
        int idx = dir ? (SS - 1 - s) : s;
        return ((size_t)(b * SS + idx)) * DM + h * HD;
    };

    auto issue = [&](int s) {
        if (s < SS) {
            size_t base = sidx(s);
            int st = s & 3;
            if (tid < 16)
                cp_async16(sb + (uint32_t)(st * 64 + tid * 4) * 4, r + base + tid * 4);
            else if (tid < 32)
                cp_async16(sb + (uint32_t)(256 + st * 64 + (tid - 16) * 4) * 4, k + base + (tid - 16) * 4);
            else if (tid < 40)
                cp_async16(sb + (uint32_t)(512 + st * 32 + (tid - 32) * 4) * 4, v + base + vh * 32 + (tid - 32) * 4);
        }
        CP_COMMIT();
    };

    issue(0); issue(1); issue(2);

    int vloc = tid >> 2;
    for (int s = 0; s < SS; s++) {
        CP_WAIT2();
        __syncthreads();
        int st = s & 3;
        float vv = s_v[st * 32 + vloc];
        const float* kr = s_k + st * 64 + kbase;
        const float* rp = s_r + st * 64 + kbase;
        float y = 0.f;
#pragma unroll
        for (int i = 0; i < 16; i++) {
            float kk  = kr[i];
            float rv  = rp[i];
            float kv  = kk * vv;
            float tmp = fmaf(ur_[i], kv, Sst[i]);
            y = fmaf(rv, tmp, y);
            Sst[i] = fmaf(wr_[i], Sst[i], kv);
        }
        y += __shfl_xor_sync(0xffffffffu, y, 1);
        y += __shfl_xor_sync(0xffffffffu, y, 2);
        if (kc == 0) yo[sidx(s) + vcol] = y;
        issue(s + 3);
    }
}

// ---------------- router ----------------
__global__ void router_k(const float* __restrict__ xn2, const float* __restrict__ rw) {
    int t = blockIdx.x, tid = threadIdx.x;
    __shared__ float sx[DM];
    __shared__ float slog[8];
    const float* xr = xn2 + (size_t)t * DM;
    for (int i = tid; i < DM; i += 256) sx[i] = xr[i];
    __syncthreads();
    int w = tid >> 5, l = tid & 31;
    float acc = 0.f;
    for (int d = l; d < DM; d += 32) acc = fmaf(sx[d], rw[d * EE + w], acc);
    for (int off = 16; off; off >>= 1) acc += __shfl_xor_sync(0xffffffffu, acc, off);
    if (l == 0) slog[w] = acc;
    __syncthreads();
    if (tid == 0) {
        float mx = -1e30f;
        for (int e = 0; e < EE; e++) mx = fmaxf(mx, slog[e]);
        float p[EE], sum = 0.f;
        for (int e = 0; e < EE; e++) { p[e] = expf(slog[e] - mx); sum += p[e]; }
        float inv = 1.f / sum;
        int e0 = 0; float b0 = -1.f;
        for (int e = 0; e < EE; e++) { p[e] *= inv; if (p[e] > b0) { b0 = p[e]; e0 = e; } }
        int e1 = -1; float b1 = -1.f;
        for (int e = 0; e < EE; e++) { if (e == e0) continue; if (p[e] > b1) { b1 = p[e]; e1 = e; } }
        float gs = 1.f / (b0 + b1);
        g_gate[2 * t]     = b0 * gs;
        g_gate[2 * t + 1] = b1 * gs;
        int pos0 = atomicAdd(&g_cnt[e0], 1); g_list[e0 * TT + pos0] = 2 * t;
        int pos1 = atomicAdd(&g_cnt[e1], 1); g_list[e1 * TT + pos1] = 2 * t + 1;
        for (int e = 0; e < EE; e++) atomicAdd(&g_pmean[e], p[e]);
    }
}

// ---------------- unified fp16 GEMM: D = A*Bh (+ A*Bl if TERMS==2) ----------------
// CTA tile BMT x 256, BK=64, 8 warps (2M x 4N), warp tile (BMT/2) x 64.
// MODE 0 = QKV (z 0..2), 1 = WO (+resid), 2 = MoE up (gather, silu -> fp16),
// MODE 3 = MoE down (gather, *gate -> fp32)
#define BNw 256
#define BKw 64
#define LDT 72
#define B_TYPE_B  (256 * LDT * 2)          // 36864 bytes
#define CLD 260

template <int BMT, int TERMS> struct HCfg {
    static constexpr int ATB   = BMT * LDT * 2;
    static constexpr int STAGE = ATB + TERMS * B_TYPE_B;
    static constexpr int SMEM  = 2 * STAGE;
};

template <int MODE, int BMT, int TERMS>
__global__ void __launch_bounds__(256, 1)
hgemm_k(const f16* __restrict__ A, const f16* __restrict__ Bh, const f16* __restrict__ Bl,
        const float* __restrict__ resid, float* __restrict__ Cf, f16* __restrict__ Ch,
        int M, int N, int K) {
    constexpr int MI   = BMT / 32;
    constexpr int AITS = BMT / 32;
    constexpr int ATB  = HCfg<BMT, TERMS>::ATB;
    constexpr int STG  = HCfg<BMT, TERMS>::STAGE;
    constexpr int NPASS = BMT / 64;

    int z = blockIdx.z;
    int bx = blockIdx.x, by = blockIdx.y;
    int Mrows = M;
    const int* list = nullptr;
    if (MODE == 2 || MODE == 3) { Mrows = g_cnt[z]; list = g_list + z * TT; }
    if (by * BMT >= Mrows) return;

    size_t boff = 0;
    if (MODE == 0) boff = (size_t)z * DM * DM;
    if (MODE == 2) boff = (size_t)z * DFFc * DM;
    if (MODE == 3) boff = (size_t)z * DM * DFFc;
    const f16* bhg = Bh + boff;
    const f16* blg = (TERMS == 2) ? Bl + boff : nullptr;
    float* cf = Cf;
    if (MODE == 0) cf = Cf + (size_t)z * TT * DM;

    extern __shared__ char smem[];
    uint32_t sb = smem_u32(smem);

    int tid = threadIdx.x;
    int wid = tid >> 5;
    int wm = wid & 1;
    int wn = wid >> 1;

    size_t a_src[AITS]; uint32_t a_so[AITS];
#pragma unroll
    for (int it = 0; it < AITS; it++) {
        int idx = tid + it * 256;
        int row = idx >> 3, seg = idx & 7;
        int ar = by * BMT + row;
        if (MODE == 2 || MODE == 3) {
            int rc = ar < Mrows ? ar : (Mrows - 1);
            int p = list[rc];
            ar = (MODE == 2) ? (p >> 1) : p;
        }
        a_src[it] = (size_t)ar * K + seg * 8;
        a_so[it] = (uint32_t)((row * LDT + seg * 8) * 2);
    }
    size_t b_src[8]; uint32_t b_so[8];
#pragma unroll
    for (int it = 0; it < 8; it++) {
        int idx = tid + it * 256;
        int row = idx >> 3, seg = idx & 7;
        b_src[it] = (size_t)(bx * BNw + row) * K + seg * 8;
        b_so[it] = (uint32_t)((row * LDT + seg * 8) * 2);
    }

    const int NC = K / BKw;
    auto issue = [&](int ci, int buf) {
        if (ci < NC) {
            int k0 = ci * BKw;
            uint32_t base = sb + buf * STG;
#pragma unroll
            for (int it = 0; it < AITS; it++)
                cp_async16(base + a_so[it], A + a_src[it] + k0);
#pragma unroll
            for (int it = 0; it < 8; it++) {
                cp_async16(base + ATB + b_so[it], bhg + b_src[it] + k0);
                if (TERMS == 2)
                    cp_async16(base + ATB + B_TYPE_B + b_so[it], blg + b_src[it] + k0);
            }
        }
        CP_COMMIT();
    };

    wmma::fragment<wmma::accumulator, 16, 16, 16, float> c[MI][4];
#pragma unroll
    for (int mi = 0; mi < MI; mi++)
#pragma unroll
        for (int ni = 0; ni < 4; ni++) wmma::fill_fragment(c[mi][ni], 0.f);

    issue(0, 0);
    issue(1, 1);

    for (int i = 0; i < NC; i++) {
        CP_WAIT1();
        __syncthreads();
        int buf = i & 1;
        const f16* sA  = (const f16*)(smem + buf * STG);
        const f16* sBh = (const f16*)(smem + buf * STG + ATB);
        const f16* sBl = (const f16*)(smem + buf * STG + ATB + B_TYPE_B);
#pragma unroll
        for (int kk = 0; kk < 4; kk++) {
            wmma::fragment<wmma::matrix_a, 16, 16, 16, f16, wmma::row_major> a[MI];
#pragma unroll
            for (int mi = 0; mi < MI; mi++)
                wmma::load_matrix_sync(a[mi], sA + (wm * (BMT / 2) + mi * 16) * LDT + kk * 16, LDT);
#pragma unroll
            for (int ni = 0; ni < 4; ni++) {
                wmma::fragment<wmma::matrix_b, 16, 16, 16, f16, wmma::col_major> bhf;
                wmma::load_matrix_sync(bhf, sBh + (wn * 64 + ni * 16) * LDT + kk * 16, LDT);
#pragma unroll
                for (int mi = 0; mi < MI; mi++)
                    wmma::mma_sync(c[mi][ni], a[mi], bhf, c[mi][ni]);
                if (TERMS == 2) {
                    wmma::fragment<wmma::matrix_b, 16, 16, 16, f16, wmma::col_major> blf;
                    wmma::load_matrix_sync(blf, sBl + (wn * 64 + ni * 16) * LDT + kk * 16, LDT);
#pragma unroll
                    for (int mi = 0; mi < MI; mi++)
                        wmma::mma_sync(c[mi][ni], a[mi], blf, c[mi][ni]);
                }
            }
        }
        __syncthreads();
        issue(i + 2, buf);
    }

    float* sC = (float*)smem;
    int lrow = tid >> 2;
    int cseg = (tid & 3) * 64;
#pragma unroll
    for (int pass = 0; pass < NPASS; pass++) {
        __syncthreads();
        if ((wm * (BMT / 2)) / 64 == pass) {
            int rbase = (wm * (BMT / 2)) % 64;
#pragma unroll
            for (int mi = 0; mi < MI; mi++)
#pragma unroll
                for (int ni = 0; ni < 4; ni++)
                    wmma::store_matrix_sync(sC + (rbase + mi * 16) * CLD + wn * 64 + ni * 16,
                                            c[mi][ni], CLD, wmma::mem_row_major);
        }
        __syncthreads();
        int arow = by * BMT + pass * 64 + lrow;
        if (arow >= Mrows) continue;
        const float* src = sC + lrow * CLD + cseg;
        int colb = bx * BNw + cseg;
        if (MODE == 2) {
            int p = list[arow];
            size_t ro = (size_t)p * DFFc + colb;
#pragma unroll
            for (int j = 0; j < 32; j++) {
                float v0 = src[2 * j], v1 = src[2 * j + 1];
                v0 = v0 / (1.f + expf(-v0));
                v1 = v1 / (1.f + expf(-v1));
                __half2 hv; hv.x = __float2half_rn(v0); hv.y = __float2half_rn(v1);
                *((__half2*)(Ch + ro) + j) = hv;
            }
        } else if (MODE == 3) {
            int p = list[arow];
            float gate = g_gate[p];
            size_t ro = (size_t)p * DM + colb;
#pragma unroll
            for (int j = 0; j < 16; j++) {
                float4 v = *(const float4*)(src + 4 * j);
                v.x *= gate; v.y *= gate; v.z *= gate; v.w *= gate;
                *(float4*)(Cf + ro + 4 * j) = v;
            }
        } else {
            size_t ro = (size_t)arow * N + colb;
#pragma unroll
            for (int j = 0; j < 16; j++) {
                float4 v = *(const float4*)(src + 4 * j);
                if (MODE == 1) {
                    float4 rs = *(const float4*)(resid + ro + 4 * j);
                    v.x += rs.x; v.y += rs.y; v.z += rs.z; v.w += rs.w;
                }
                *(float4*)(cf + ro + 4 * j) = v;
            }
        }
    }
}

// ---------------- finalize ----------------
__global__ void finalize_k(float* __restrict__ out, int out_size) {
    int t = blockIdx.x;
    for (int i = threadIdx.x; i < DM; i += 256) {
        size_t o = (size_t)t * DM + i;
        out[o] = g_x1[o] + g_moe[(size_t)(2 * t) * DM + i] + g_moe[(size_t)(2 * t + 1) * DM + i];
    }
    if (blockIdx.x == 0 && threadIdx.x == 0 && out_size > TT * DM) {
        float aux = 0.f;
        for (int e = 0; e < EE; e++)
            aux += ((float)g_cnt[e] / (float)(TT * 2)) * (g_pmean[e] / (float)TT);
        out[out_size - 1] = aux * (float)EE;
    }
}

// ---------------- host launcher ----------------
extern "C" void kernel_launch(void* const* d_in, const int* in_sizes, int n_in,
                              void* d_out, int out_size) {
    const float* x     = (const float*)d_in[0];
    const float* n1w   = (const float*)d_in[2];
    const float* n2w   = (const float*)d_in[3];
    const float* Wr    = (const float*)d_in[4];
    const float* Wk    = (const float*)d_in[5];
    const float* Wv    = (const float*)d_in[6];
    const float* Wo    = (const float*)d_in[7];
    const float* decay = (const float*)d_in[8];
    const float* bonus = (const float*)d_in[9];
    const float* rw    = (const float*)d_in[10];
    const float* w1    = (const float*)d_in[11];
    const float* w2    = (const float*)d_in[12];
    float* out = (float*)d_out;

    float *rkv, *yf, *yb, *x1, *xn2, *moe;
    f16 *xn1f, *yaf, *xn2f, *hf;
    f16 *wqkvfh, *wqkvfl, *wofh, *wofl, *w1f, *w2f;
    cudaGetSymbolAddress((void**)&rkv,  g_rkv);
    cudaGetSymbolAddress((void**)&yf,   g_yf);
    cudaGetSymbolAddress((void**)&yb,   g_yb);
    cudaGetSymbolAddress((void**)&x1,   g_x1);
    cudaGetSymbolAddress((void**)&xn2,  g_xn2);
    cudaGetSymbolAddress((void**)&moe,  g_moe);
    cudaGetSymbolAddress((void**)&xn1f, g_xn1f);
    cudaGetSymbolAddress((void**)&yaf,  g_yaf);
    cudaGetSymbolAddress((void**)&xn2f, g_xn2f);
    cudaGetSymbolAddress((void**)&hf,   g_hf);
    cudaGetSymbolAddress((void**)&wqkvfh, g_wqkvfh);
    cudaGetSymbolAddress((void**)&wqkvfl, g_wqkvfl);
    cudaGetSymbolAddress((void**)&wofh, g_wofh);
    cudaGetSymbolAddress((void**)&wofl, g_wofl);
    cudaGetSymbolAddress((void**)&w1f,  g_w1f);
    cudaGetSymbolAddress((void**)&w2f,  g_w2f);

    cudaFuncSetAttribute(hgemm_k<0, 128, 2>, cudaFuncAttributeMaxDynamicSharedMemorySize, HCfg<128, 2>::SMEM);
    cudaFuncSetAttribute(hgemm_k<1, 64, 2>,  cudaFuncAttributeMaxDynamicSharedMemorySize, HCfg<64, 2>::SMEM);
    cudaFuncSetAttribute(hgemm_k<2, 128, 1>, cudaFuncAttributeMaxDynamicSharedMemorySize, HCfg<128, 1>::SMEM);
    cudaFuncSetAttribute(hgemm_k<3, 128, 1>, cudaFuncAttributeMaxDynamicSharedMemorySize, HCfg<128, 1>::SMEM);

    zero_k<<<1, 32>>>();

    dim3 tb(32, 8);
    tsplit16_k<true><<<dim3(DM / 32, DM / 32, 1), tb>>>(Wr, wqkvfh,               wqkvfl,               DM, DM);
    tsplit16_k<true><<<dim3(DM / 32, DM / 32, 1), tb>>>(Wk, wqkvfh + DM * DM,     wqkvfl + DM * DM,     DM, DM);
    tsplit16_k<true><<<dim3(DM / 32, DM / 32, 1), tb>>>(Wv, wqkvfh + 2 * DM * DM, wqkvfl + 2 * DM * DM, DM, DM);

    rmsnorm_k<false><<<TT, 256>>>(x, n1w, nullptr, xn1f);

    // QKV (fp16 2-term)
    hgemm_k<0, 128, 2><<<dim3(DM / BNw, TT / 128, 3), 256, HCfg<128, 2>::SMEM>>>(
        xn1f, wqkvfh, wqkvfl, nullptr, rkv, nullptr, TT, DM, DM);

    scan_k<<<dim3(HH * 2, BB, 2), 128>>>(rkv, rkv + TT * DM, rkv + 2 * TT * DM, decay, bonus);

    tsplit16_k<true><<<dim3(DM / 32, DM / 32, 1), tb>>>(Wo, wofh, wofl, DM, DM);

    addcvt_k<<<(TT * DM + 255) / 256, 256>>>(yf, yb, yaf, TT * DM);

    // x1 = x + (yf+yb) @ Wo (fp16 2-term)
    hgemm_k<1, 64, 2><<<dim3(DM / BNw, TT / 64, 1), 256, HCfg<64, 2>::SMEM>>>(
        yaf, wofh, wofl, x, x1, nullptr, TT, DM, DM);

    rmsnorm_k<true><<<TT, 256>>>(x1, n2w, xn2, xn2f);
    router_k<<<TT, 256>>>(xn2, rw);

    tsplit16_k<false><<<dim3(DFFc / 32, DM / 32, EE), tb>>>(w1, w1f, nullptr, DM, DFFc);

    // MoE up (fp16 1-term): h[p] = silu(xn2f[token] @ w1f[e]) -> fp16
    hgemm_k<2, 128, 1><<<dim3(DFFc / BNw, TT / 128, EE), 256, HCfg<128, 1>::SMEM>>>(
        xn2f, w1f, nullptr, nullptr, nullptr, hf, 0, DFFc, DM);

    tsplit16_k<false><<<dim3(DM / 32, DFFc / 32, EE), tb>>>(w2, w2f, nullptr, DFFc, DM);

    // MoE down (fp16 1-term): moe[p] = gate[p] * (hf[p] @ w2f[e])
    hgemm_k<3, 128, 1><<<dim3(DM / BNw, TT / 128, EE), 256, HCfg<128, 1>::SMEM>>>(
        hf, w2f, nullptr, nullptr, moe, nullptr, 0, DM, DFFc);

    finalize_k<<<TT, 256>>>(out, out_size);
}

// round 17
// speedup vs baseline: 1.9794x; 1.0745x over previous
#include <cuda_runtime.h>
#include <cuda_fp16.h>
#include <mma.h>
#include <math.h>
#include <stdint.h>

using namespace nvcuda;

// Problem constants
#define TT   4096
#define DM   1024
#define HH   16
#define HD   64
#define DFFc 2048
#define EE   8
#define SS   2048
#define BB   2

typedef __half f16;

// ---------------- scratch ----------------
__device__ float g_rkv[3 * TT * DM];
__device__ float g_yf[TT * DM];
__device__ float g_yb[TT * DM];
__device__ float g_x1[TT * DM];
__device__ float g_xn2[TT * DM];
__device__ float g_moe[2 * TT * DM];
__device__ f16   g_xn1f[TT * DM];
__device__ f16   g_yaf[TT * DM];
__device__ f16   g_xn2f[TT * DM];
__device__ f16   g_hf[2 * TT * DFFc];            // 32 MB
__device__ f16   g_wqkvf[3 * DM * DM];
__device__ f16   g_wof[DM * DM];
__device__ f16   g_w1f[EE * DFFc * DM];
__device__ f16   g_w2f[EE * DM * DFFc];
__device__ float g_gate[2 * TT];
__device__ int   g_list[EE * TT];
__device__ int   g_cnt[EE];
__device__ float g_pmean[EE];

__device__ __forceinline__ uint32_t smem_u32(const void* p) {
    uint32_t a;
    asm("{ .reg .u64 t; cvta.to.shared.u64 t, %1; cvt.u32.u64 %0, t; }" : "=r"(a) : "l"(p));
    return a;
}
__device__ __forceinline__ void cp_async16(uint32_t s, const void* g) {
    asm volatile("cp.async.cg.shared.global [%0], [%1], 16;" :: "r"(s), "l"(g) : "memory");
}
#define CP_COMMIT() asm volatile("cp.async.commit_group;" ::: "memory")
#define CP_WAIT1()  asm volatile("cp.async.wait_group 1;"  ::: "memory")
#define CP_WAIT2()  asm volatile("cp.async.wait_group 2;"  ::: "memory")

// ---------------- small kernels ----------------
__global__ void zero_k() {
    int i = threadIdx.x;
    if (i < EE) { g_cnt[i] = 0; g_pmean[i] = 0.f; }
}

// transpose + convert fp16: src [K,N] fp32 (batch z) -> d [N,K] fp16
__global__ void tcvt16_k(const float* __restrict__ src, f16* __restrict__ d, int K, int N) {
    int e = blockIdx.z;
    src += (size_t)e * K * N;
    d   += (size_t)e * N * K;
    __shared__ float tile[32][33];
    int n0 = blockIdx.x * 32, k0 = blockIdx.y * 32;
    int tx = threadIdx.x, ty = threadIdx.y;
#pragma unroll
    for (int i = 0; i < 4; i++)
        tile[ty + i * 8][tx] = src[(size_t)(k0 + ty + i * 8) * N + n0 + tx];
    __syncthreads();
    int t = ty * 32 + tx;
#pragma unroll
    for (int it = 0; it < 2; it++) {
        int i = t + it * 256;
        int row = i >> 4;
        int kp  = i & 15;
        __half2 hv;
        hv.x = __float2half_rn(tile[kp * 2][row]);
        hv.y = __float2half_rn(tile[kp * 2 + 1][row]);
        size_t o = ((size_t)(n0 + row) * K + k0 + kp * 2) >> 1;
        ((__half2*)d)[o] = hv;
    }
}

// ya = fp16(yf + yb)
__global__ void addcvt_k(const float* __restrict__ a, const float* __restrict__ b,
                         f16* __restrict__ o, int n) {
    int i = blockIdx.x * blockDim.x + threadIdx.x;
    if (i >= n) return;
    o[i] = __float2half_rn(a[i] + b[i]);
}

// rmsnorm -> fp16 (+ optional fp32 for router)
template <bool WRITE_F32>
__global__ void rmsnorm_k(const float* __restrict__ x, const float* __restrict__ w,
                          float* __restrict__ ofp, f16* __restrict__ o16) {
    int t = blockIdx.x;
    const float* xr = x + (size_t)t * DM;
    float s = 0.f;
    for (int i = threadIdx.x; i < DM; i += 256) { float v = xr[i]; s += v * v; }
    for (int off = 16; off; off >>= 1) s += __shfl_xor_sync(0xffffffffu, s, off);
    __shared__ float red[8];
    int wrp = threadIdx.x >> 5, ln = threadIdx.x & 31;
    if (ln == 0) red[wrp] = s;
    __syncthreads();
    if (wrp == 0) {
        float v = (ln < 8) ? red[ln] : 0.f;
        for (int off = 4; off; off >>= 1) v += __shfl_xor_sync(0xffffffffu, v, off);
        if (ln == 0) red[0] = v;
    }
    __syncthreads();
    float scale = rsqrtf(red[0] / (float)DM + 1e-6f);
    size_t base = (size_t)t * DM;
    for (int i = threadIdx.x; i < DM; i += 256) {
        float v = xr[i] * scale * w[i];
        if (WRITE_F32) ofp[base + i] = v;
        o16[base + i] = __float2half_rn(v);
    }
}

// ---------------- RWKV bidirectional scan, 4-stage cp.async pipeline ----------------
__global__ void scan_k(const float* __restrict__ r, const float* __restrict__ k,
                       const float* __restrict__ v,
                       const float* __restrict__ decay, const float* __restrict__ bonus) {
    int h  = blockIdx.x >> 1;
    int vh = blockIdx.x & 1;
    int b  = blockIdx.y;
    int dir = blockIdx.z;
    int tid = threadIdx.x;
    int vcol  = vh * 32 + (tid >> 2);
    int kc    = tid & 3;
    int kbase = kc * 16;

    float Sst[16], wr_[16], ur_[16];
#pragma unroll
    for (int i = 0; i < 16; i++) {
        Sst[i] = 0.f;
        float d = decay[h * HD + kbase + i];
        wr_[i] = expf(-expf(d));
        ur_[i] = bonus[h * HD + kbase + i];
    }
    float* yo = dir ? g_yb : g_yf;

    __shared__ float sbuf[4 * 64 + 4 * 64 + 4 * 32];
    float* s_r = sbuf;
    float* s_k = sbuf + 256;
    float* s_v = sbuf + 512;
    uint32_t sb = smem_u32(sbuf);

    auto sidx = [&](int s) -> size_t {
        int idx = dir ? (SS - 1 - s) : s;
        return ((size_t)(b * SS + idx)) * DM + h * HD;
    };

    auto issue = [&](int s) {
        if (s < SS) {
            size_t base = sidx(s);
            int st = s & 3;
            if (tid < 16)
                cp_async16(sb + (uint32_t)(st * 64 + tid * 4) * 4, r + base + tid * 4);
            else if (tid < 32)
                cp_async16(sb + (uint32_t)(256 + st * 64 + (tid - 16) * 4) * 4, k + base + (tid - 16) * 4);
            else if (tid < 40)
                cp_async16(sb + (uint32_t)(512 + st * 32 + (tid - 32) * 4) * 4, v + base + vh * 32 + (tid - 32) * 4);
        }
        CP_COMMIT();
    };

    issue(0); issue(1); issue(2);

    int vloc = tid >> 2;
    for (int s = 0; s < SS; s++) {
        CP_WAIT2();
        __syncthreads();
        int st = s & 3;
        float vv = s_v[st * 32 + vloc];
        const float* kr = s_k + st * 64 + kbase;
        const float* rp = s_r + st * 64 + kbase;
        float y = 0.f;
#pragma unroll
        for (int i = 0; i < 16; i++) {
            float kk  = kr[i];
            float rv  = rp[i];
            float kv  = kk * vv;
            float tmp = fmaf(ur_[i], kv, Sst[i]);
            y = fmaf(rv, tmp, y);
            Sst[i] = fmaf(wr_[i], Sst[i], kv);
        }
        y += __shfl_xor_sync(0xffffffffu, y, 1);
        y += __shfl_xor_sync(0xffffffffu, y, 2);
        if (kc == 0) yo[sidx(s) + vcol] = y;
        issue(s + 3);
    }
}

// ---------------- router ----------------
__global__ void router_k(const float* __restrict__ xn2, const float* __restrict__ rw) {
    int t = blockIdx.x, tid = threadIdx.x;
    __shared__ float sx[DM];
    __shared__ float slog[8];
    const float* xr = xn2 + (size_t)t * DM;
    for (int i = tid; i < DM; i += 256) sx[i] = xr[i];
    __syncthreads();
    int w = tid >> 5, l = tid & 31;
    float acc = 0.f;
    for (int d = l; d < DM; d += 32) acc = fmaf(sx[d], rw[d * EE + w], acc);
    for (int off = 16; off; off >>= 1) acc += __shfl_xor_sync(0xffffffffu, acc, off);
    if (l == 0) slog[w] = acc;
    __syncthreads();
    if (tid == 0) {
        float mx = -1e30f;
        for (int e = 0; e < EE; e++) mx = fmaxf(mx, slog[e]);
        float p[EE], sum = 0.f;
        for (int e = 0; e < EE; e++) { p[e] = expf(slog[e] - mx); sum += p[e]; }
        float inv = 1.f / sum;
        int e0 = 0; float b0 = -1.f;
        for (int e = 0; e < EE; e++) { p[e] *= inv; if (p[e] > b0) { b0 = p[e]; e0 = e; } }
        int e1 = -1; float b1 = -1.f;
        for (int e = 0; e < EE; e++) { if (e == e0) continue; if (p[e] > b1) { b1 = p[e]; e1 = e; } }
        float gs = 1.f / (b0 + b1);
        g_gate[2 * t]     = b0 * gs;
        g_gate[2 * t + 1] = b1 * gs;
        int pos0 = atomicAdd(&g_cnt[e0], 1); g_list[e0 * TT + pos0] = 2 * t;
        int pos1 = atomicAdd(&g_cnt[e1], 1); g_list[e1 * TT + pos1] = 2 * t + 1;
        for (int e = 0; e < EE; e++) atomicAdd(&g_pmean[e], p[e]);
    }
}

// ---------------- unified fp16 1-term GEMM: D = A*B ----------------
// CTA tile BMT x 256, BK=64, 8 warps (2M x 4N), warp tile (BMT/2) x 64.
// MODE 0 = QKV (z 0..2), 1 = WO (+resid), 2 = MoE up (gather, silu -> fp16),
// MODE 3 = MoE down (gather, *gate -> fp32)
#define BNw 256
#define BKw 64
#define LDT 72
#define B_TYPE_B  (256 * LDT * 2)          // 36864 bytes
#define CLD 260

template <int BMT> struct HCfg {
    static constexpr int ATB   = BMT * LDT * 2;
    static constexpr int STAGE = ATB + B_TYPE_B;
    static constexpr int SMEM  = 2 * STAGE;
};

template <int MODE, int BMT>
__global__ void __launch_bounds__(256, 1)
hgemm_k(const f16* __restrict__ A, const f16* __restrict__ B,
        const float* __restrict__ resid, float* __restrict__ Cf, f16* __restrict__ Ch,
        int M, int N, int K) {
    constexpr int MI   = BMT / 32;
    constexpr int AITS = BMT / 32;
    constexpr int ATB  = HCfg<BMT>::ATB;
    constexpr int STG  = HCfg<BMT>::STAGE;
    constexpr int NPASS = BMT / 64;

    int z = blockIdx.z;
    int bx = blockIdx.x, by = blockIdx.y;
    int Mrows = M;
    const int* list = nullptr;
    if (MODE == 2 || MODE == 3) { Mrows = g_cnt[z]; list = g_list + z * TT; }
    if (by * BMT >= Mrows) return;

    size_t boff = 0;
    if (MODE == 0) boff = (size_t)z * DM * DM;
    if (MODE == 2) boff = (size_t)z * DFFc * DM;
    if (MODE == 3) boff = (size_t)z * DM * DFFc;
    const f16* bg = B + boff;
    float* cf = Cf;
    if (MODE == 0) cf = Cf + (size_t)z * TT * DM;

    extern __shared__ char smem[];
    uint32_t sb = smem_u32(smem);

    int tid = threadIdx.x;
    int wid = tid >> 5;
    int wm = wid & 1;
    int wn = wid >> 1;

    size_t a_src[AITS]; uint32_t a_so[AITS];
#pragma unroll
    for (int it = 0; it < AITS; it++) {
        int idx = tid + it * 256;
        int row = idx >> 3, seg = idx & 7;
        int ar = by * BMT + row;
        if (MODE == 2 || MODE == 3) {
            int rc = ar < Mrows ? ar : (Mrows - 1);
            int p = list[rc];
            ar = (MODE == 2) ? (p >> 1) : p;
        }
        a_src[it] = (size_t)ar * K + seg * 8;
        a_so[it] = (uint32_t)((row * LDT + seg * 8) * 2);
    }
    size_t b_src[8]; uint32_t b_so[8];
#pragma unroll
    for (int it = 0; it < 8; it++) {
        int idx = tid + it * 256;
        int row = idx >> 3, seg = idx & 7;
        b_src[it] = (size_t)(bx * BNw + row) * K + seg * 8;
        b_so[it] = (uint32_t)((row * LDT + seg * 8) * 2);
    }

    const int NC = K / BKw;
    auto issue = [&](int ci, int buf) {
        if (ci < NC) {
            int k0 = ci * BKw;
            uint32_t base = sb + buf * STG;
#pragma unroll
            for (int it = 0; it < AITS; it++)
                cp_async16(base + a_so[it], A + a_src[it] + k0);
#pragma unroll
            for (int it = 0; it < 8; it++)
                cp_async16(base + ATB + b_so[it], bg + b_src[it] + k0);
        }
        CP_COMMIT();
    };

    wmma::fragment<wmma::accumulator, 16, 16, 16, float> c[MI][4];
#pragma unroll
    for (int mi = 0; mi < MI; mi++)
#pragma unroll
        for (int ni = 0; ni < 4; ni++) wmma::fill_fragment(c[mi][ni], 0.f);

    issue(0, 0);
    issue(1, 1);

    for (int i = 0; i < NC; i++) {
        CP_WAIT1();
        __syncthreads();
        int buf = i & 1;
        const f16* sA = (const f16*)(smem + buf * STG);
        const f16* sB = (const f16*)(smem + buf * STG + ATB);
#pragma unroll
        for (int kk = 0; kk < 4; kk++) {
            wmma::fragment<wmma::matrix_a, 16, 16, 16, f16, wmma::row_major> a[MI];
#pragma unroll
            for (int mi = 0; mi < MI; mi++)
                wmma::load_matrix_sync(a[mi], sA + (wm * (BMT / 2) + mi * 16) * LDT + kk * 16, LDT);
#pragma unroll
            for (int ni = 0; ni < 4; ni++) {
                wmma::fragment<wmma::matrix_b, 16, 16, 16, f16, wmma::col_major> bf;
                wmma::load_matrix_sync(bf, sB + (wn * 64 + ni * 16) * LDT + kk * 16, LDT);
#pragma unroll
                for (int mi = 0; mi < MI; mi++)
                    wmma::mma_sync(c[mi][ni], a[mi], bf, c[mi][ni]);
            }
        }
        __syncthreads();
        issue(i + 2, buf);
    }

    float* sC = (float*)smem;
    int lrow = tid >> 2;
    int cseg = (tid & 3) * 64;
#pragma unroll
    for (int pass = 0; pass < NPASS; pass++) {
        __syncthreads();
        if ((wm * (BMT / 2)) / 64 == pass) {
            int rbase = (wm * (BMT / 2)) % 64;
#pragma unroll
            for (int mi = 0; mi < MI; mi++)
#pragma unroll
                for (int ni = 0; ni < 4; ni++)
                    wmma::store_matrix_sync(sC + (rbase + mi * 16) * CLD + wn * 64 + ni * 16,
                                            c[mi][ni], CLD, wmma::mem_row_major);
        }
        __syncthreads();
        int arow = by * BMT + pass * 64 + lrow;
        if (arow >= Mrows) continue;
        const float* src = sC + lrow * CLD + cseg;
        int colb = bx * BNw + cseg;
        if (MODE == 2) {
            int p = list[arow];
            size_t ro = (size_t)p * DFFc + colb;
#pragma unroll
            for (int j = 0; j < 32; j++) {
                float v0 = src[2 * j], v1 = src[2 * j + 1];
                v0 = v0 / (1.f + expf(-v0));
                v1 = v1 / (1.f + expf(-v1));
                __half2 hv; hv.x = __float2half_rn(v0); hv.y = __float2half_rn(v1);
                *((__half2*)(Ch + ro) + j) = hv;
            }
        } else if (MODE == 3) {
            int p = list[arow];
            float gate = g_gate[p];
            size_t ro = (size_t)p * DM + colb;
#pragma unroll
            for (int j = 0; j < 16; j++) {
                float4 v = *(const float4*)(src + 4 * j);
                v.x *= gate; v.y *= gate; v.z *= gate; v.w *= gate;
                *(float4*)(Cf + ro + 4 * j) = v;
            }
        } else {
            size_t ro = (size_t)arow * N + colb;
#pragma unroll
            for (int j = 0; j < 16; j++) {
                float4 v = *(const float4*)(src + 4 * j);
                if (MODE == 1) {
                    float4 rs = *(const float4*)(resid + ro + 4 * j);
                    v.x += rs.x; v.y += rs.y; v.z += rs.z; v.w += rs.w;
                }
                *(float4*)(cf + ro + 4 * j) = v;
            }
        }
    }
}

// ---------------- finalize ----------------
__global__ void finalize_k(float* __restrict__ out, int out_size) {
    int t = blockIdx.x;
    for (int i = threadIdx.x; i < DM; i += 256) {
        size_t o = (size_t)t * DM + i;
        out[o] = g_x1[o] + g_moe[(size_t)(2 * t) * DM + i] + g_moe[(size_t)(2 * t + 1) * DM + i];
    }
    if (blockIdx.x == 0 && threadIdx.x == 0 && out_size > TT * DM) {
        float aux = 0.f;
        for (int e = 0; e < EE; e++)
            aux += ((float)g_cnt[e] / (float)(TT * 2)) * (g_pmean[e] / (float)TT);
        out[out_size - 1] = aux * (float)EE;
    }
}

// ---------------- host launcher ----------------
extern "C" void kernel_launch(void* const* d_in, const int* in_sizes, int n_in,
                              void* d_out, int out_size) {
    const float* x     = (const float*)d_in[0];
    const float* n1w   = (const float*)d_in[2];
    const float* n2w   = (const float*)d_in[3];
    const float* Wr    = (const float*)d_in[4];
    const float* Wk    = (const float*)d_in[5];
    const float* Wv    = (const float*)d_in[6];
    const float* Wo    = (const float*)d_in[7];
    const float* decay = (const float*)d_in[8];
    const float* bonus = (const float*)d_in[9];
    const float* rw    = (const float*)d_in[10];
    const float* w1    = (const float*)d_in[11];
    const float* w2    = (const float*)d_in[12];
    float* out = (float*)d_out;

    float *rkv, *yf, *yb, *x1, *xn2, *moe;
    f16 *xn1f, *yaf, *xn2f, *hf, *wqkvf, *wof, *w1f, *w2f;
    cudaGetSymbolAddress((void**)&rkv,  g_rkv);
    cudaGetSymbolAddress((void**)&yf,   g_yf);
    cudaGetSymbolAddress((void**)&yb,   g_yb);
    cudaGetSymbolAddress((void**)&x1,   g_x1);
    cudaGetSymbolAddress((void**)&xn2,  g_xn2);
    cudaGetSymbolAddress((void**)&moe,  g_moe);
    cudaGetSymbolAddress((void**)&xn1f, g_xn1f);
    cudaGetSymbolAddress((void**)&yaf,  g_yaf);
    cudaGetSymbolAddress((void**)&xn2f, g_xn2f);
    cudaGetSymbolAddress((void**)&hf,   g_hf);
    cudaGetSymbolAddress((void**)&wqkvf, g_wqkvf);
    cudaGetSymbolAddress((void**)&wof,  g_wof);
    cudaGetSymbolAddress((void**)&w1f,  g_w1f);
    cudaGetSymbolAddress((void**)&w2f,  g_w2f);

    cudaFuncSetAttribute(hgemm_k<0, 128>, cudaFuncAttributeMaxDynamicSharedMemorySize, HCfg<128>::SMEM);
    cudaFuncSetAttribute(hgemm_k<1, 64>,  cudaFuncAttributeMaxDynamicSharedMemorySize, HCfg<64>::SMEM);
    cudaFuncSetAttribute(hgemm_k<2, 128>, cudaFuncAttributeMaxDynamicSharedMemorySize, HCfg<128>::SMEM);
    cudaFuncSetAttribute(hgemm_k<3, 128>, cudaFuncAttributeMaxDynamicSharedMemorySize, HCfg<128>::SMEM);

    zero_k<<<1, 32>>>();

    dim3 tb(32, 8);
    tcvt16_k<<<dim3(DM / 32, DM / 32, 1), tb>>>(Wr, wqkvf,               DM, DM);
    tcvt16_k<<<dim3(DM / 32, DM / 32, 1), tb>>>(Wk, wqkvf + DM * DM,     DM, DM);
    tcvt16_k<<<dim3(DM / 32, DM / 32, 1), tb>>>(Wv, wqkvf + 2 * DM * DM, DM, DM);

    rmsnorm_k<false><<<TT, 256>>>(x, n1w, nullptr, xn1f);

    // QKV (fp16 1-term)
    hgemm_k<0, 128><<<dim3(DM / BNw, TT / 128, 3), 256, HCfg<128>::SMEM>>>(
        xn1f, wqkvf, nullptr, rkv, nullptr, TT, DM, DM);

    scan_k<<<dim3(HH * 2, BB, 2), 128>>>(rkv, rkv + TT * DM, rkv + 2 * TT * DM, decay, bonus);

    tcvt16_k<<<dim3(DM / 32, DM / 32, 1), tb>>>(Wo, wof, DM, DM);

    addcvt_k<<<(TT * DM + 255) / 256, 256>>>(yf, yb, yaf, TT * DM);

    // x1 = x + (yf+yb) @ Wo (fp16 1-term)
    hgemm_k<1, 64><<<dim3(DM / BNw, TT / 64, 1), 256, HCfg<64>::SMEM>>>(
        yaf, wof, x, x1, nullptr, TT, DM, DM);

    rmsnorm_k<true><<<TT, 256>>>(x1, n2w, xn2, xn2f);
    router_k<<<TT, 256>>>(xn2, rw);

    tcvt16_k<<<dim3(DFFc / 32, DM / 32, EE), tb>>>(w1, w1f, DM, DFFc);

    // MoE up (fp16 1-term): h[p] = silu(xn2f[token] @ w1f[e]) -> fp16
    hgemm_k<2, 128><<<dim3(DFFc / BNw, TT / 128, EE), 256, HCfg<128>::SMEM>>>(
        xn2f, w1f, nullptr, nullptr, hf, 0, DFFc, DM);

    tcvt16_k<<<dim3(DM / 32, DFFc / 32, EE), tb>>>(w2, w2f, DFFc, DM);

    // MoE down (fp16 1-term): moe[p] = gate[p] * (hf[p] @ w2f[e])
    hgemm_k<3, 128><<<dim3(DM / BNw, TT / 128, EE), 256, HCfg<128>::SMEM>>>(
        hf, w2f, nullptr, moe, nullptr, 0, DM, DFFc);

    finalize_k<<<TT, 256>>>(out, out_size);
}